// round 13
// baseline (speedup 1.0000x reference)
#include <cuda_runtime.h>
#include <cuda_fp16.h>
#include <math.h>
#include <stdint.h>

// ---------------- problem constants ----------------
#define RESV   32
#define L_TOT  (RESV*RESV*RESV)      // 32768
#define BATCH  2
#define CDIM   288
#define QKV_N  (3*CDIM)              // 864
#define NROWS  (BATCH*L_TOT)         // 65536
#define HB     4
#define HDIM   24
#define NWIN   16
#define TBIAS  63

// scratch (no cudaMalloc allowed) — fp16 intermediates
__device__ __half g_xh  [(size_t)NROWS * CDIM];
__device__ __half g_qkv [(size_t)NROWS * QKV_N];
__device__ __half g_y   [(size_t)NROWS * CDIM];
__device__ __half g_vc  [(size_t)BATCH * CDIM * L_TOT];  // v, channel-major
__device__ __half g_lcm [(size_t)BATCH * CDIM * L_TOT];  // conv out, channel-major
__device__ __half g_wqkvT[(size_t)QKV_N * CDIM];
__device__ __half g_wprojT[(size_t)CDIM * CDIM];
__device__ float  g_bias[3 * HB * NWIN * NWIN];

__constant__ int c_Dsp[3] = {2, 2, 2};
__constant__ int c_Hsp[3] = {2, 2, 4};
__constant__ int c_Wsp[3] = {4, 4, 2};

// ==================== helpers ====================
__device__ __forceinline__ uint32_t smem_u32_of(const void* p) {
    uint32_t a;
    asm("{ .reg .u64 t; cvta.to.shared.u64 t, %1; cvt.u32.u64 %0, t; }" : "=r"(a) : "l"(p));
    return a;
}

__device__ __forceinline__ void mma16(float* d,
                                      uint32_t a0, uint32_t a1, uint32_t a2, uint32_t a3,
                                      uint32_t b0, uint32_t b1) {
    asm volatile("mma.sync.aligned.m16n8k16.row.col.f32.f16.f16.f32 "
                 "{%0,%1,%2,%3}, {%4,%5,%6,%7}, {%8,%9}, {%0,%1,%2,%3};"
                 : "+f"(d[0]), "+f"(d[1]), "+f"(d[2]), "+f"(d[3])
                 : "r"(a0), "r"(a1), "r"(a2), "r"(a3), "r"(b0), "r"(b1));
}

__device__ __forceinline__ void ldsm4(uint32_t& r0, uint32_t& r1, uint32_t& r2, uint32_t& r3,
                                      uint32_t addr) {
    asm volatile("ldmatrix.sync.aligned.m8n8.x4.shared.b16 {%0,%1,%2,%3}, [%4];"
                 : "=r"(r0), "=r"(r1), "=r"(r2), "=r"(r3) : "r"(addr));
}

__device__ __forceinline__ void ldsm4t(uint32_t& r0, uint32_t& r1, uint32_t& r2, uint32_t& r3,
                                       uint32_t addr) {
    asm volatile("ldmatrix.sync.aligned.m8n8.x4.trans.shared.b16 {%0,%1,%2,%3}, [%4];"
                 : "=r"(r0), "=r"(r1), "=r"(r2), "=r"(r3) : "r"(addr));
}

__device__ __forceinline__ uint32_t pack_h2(float x, float y) {
    __half2 h = __floats2half2_rn(x, y);
    return *(uint32_t*)&h;
}

#define CP16(dst, src) \
    asm volatile("cp.async.cg.shared.global [%0], [%1], 16;" :: "r"(dst), "l"(src))
#define CP_COMMIT() asm volatile("cp.async.commit_group;")
#define CP_WAIT2()  asm volatile("cp.async.wait_group 2;")
#define CP_WAIT1()  asm volatile("cp.async.wait_group 1;")
#define CP_WAIT0()  asm volatile("cp.async.wait_group 0;")

// ==================== RPE-bias MLP piece ====================
__device__ __forceinline__ void ln_relu6(float* h, const float* g, const float* b) {
    float m = 0.f;
#pragma unroll
    for (int j = 0; j < 6; j++) m += h[j];
    m *= (1.0f / 6.0f);
    float v = 0.f;
#pragma unroll
    for (int j = 0; j < 6; j++) { float d = h[j] - m; v += d * d; }
    v *= (1.0f / 6.0f);
    float inv = rsqrtf(v + 1e-5f);
#pragma unroll
    for (int j = 0; j < 6; j++) {
        float t = (h[j] - m) * inv * g[j] + b[j];
        h[j] = t > 0.f ? t : 0.f;
    }
}

// ==================== fused prep: biasmlp + x->half + weight transposes ====================
#define BM_BLOCKS  3
#define X2H_BLOCKS 9216
#define TQ_BLOCKS  (27 * 9)
#define TP_BLOCKS  (9 * 9)
#define PREP_BLOCKS (BM_BLOCKS + X2H_BLOCKS + TQ_BLOCKS + TP_BLOCKS)

__global__ __launch_bounds__(256)
void prep_kernel(const float* __restrict__ x, __half* __restrict__ xh,
                 const float* __restrict__ wq, __half* __restrict__ wqT,
                 const float* __restrict__ wp, __half* __restrict__ wpT,
                 const float* __restrict__ rpe,
                 const float* __restrict__ pw, const float* __restrict__ pb,
                 const float* __restrict__ g1, const float* __restrict__ be1,
                 const float* __restrict__ w1, const float* __restrict__ b1,
                 const float* __restrict__ g2, const float* __restrict__ be2,
                 const float* __restrict__ w2, const float* __restrict__ b2,
                 const float* __restrict__ g3, const float* __restrict__ be3,
                 const float* __restrict__ w3, const float* __restrict__ b3,
                 const int* __restrict__ relidx, float* __restrict__ biasb) {
    __shared__ float tt[32][33];
    __shared__ float p[TBIAS][HB];
    const int bid = blockIdx.x, tid = threadIdx.x;

    if (bid < BM_BLOCKS) {
        const int bi = bid;
        if (tid < TBIAS) {
            float h[6], tmp[6];
            const float* r = rpe + (bi * TBIAS + tid) * 3;
            float r0 = r[0], r1 = r[1], r2 = r[2];
#pragma unroll
            for (int j = 0; j < 6; j++)
                h[j] = pb[bi * 6 + j]
                     + r0 * pw[(bi * 3 + 0) * 6 + j]
                     + r1 * pw[(bi * 3 + 1) * 6 + j]
                     + r2 * pw[(bi * 3 + 2) * 6 + j];
            ln_relu6(h, g1 + bi * 6, be1 + bi * 6);
#pragma unroll
            for (int j = 0; j < 6; j++) {
                float s = b1[bi * 6 + j];
#pragma unroll
                for (int i = 0; i < 6; i++) s += h[i] * w1[(bi * 6 + i) * 6 + j];
                tmp[j] = s;
            }
#pragma unroll
            for (int j = 0; j < 6; j++) h[j] = tmp[j];
            ln_relu6(h, g2 + bi * 6, be2 + bi * 6);
#pragma unroll
            for (int j = 0; j < 6; j++) {
                float s = b2[bi * 6 + j];
#pragma unroll
                for (int i = 0; i < 6; i++) s += h[i] * w2[(bi * 6 + i) * 6 + j];
                tmp[j] = s;
            }
#pragma unroll
            for (int j = 0; j < 6; j++) h[j] = tmp[j];
            ln_relu6(h, g3 + bi * 6, be3 + bi * 6);
#pragma unroll
            for (int j = 0; j < HB; j++) {
                float s = b3[bi * HB + j];
#pragma unroll
                for (int i = 0; i < 6; i++) s += h[i] * w3[(bi * 6 + i) * HB + j];
                p[tid][j] = s;
            }
        }
        __syncthreads();
        for (int i = tid; i < HB * NWIN * NWIN; i += blockDim.x) {
            int hb = i >> 8;
            int nm = i & 255;
            biasb[bi * (HB * NWIN * NWIN) + i] = p[relidx[bi * 256 + nm]][hb];
        }
        return;
    }

    if (bid < BM_BLOCKS + X2H_BLOCKS) {
        size_t i = ((size_t)(bid - BM_BLOCKS) * 256 + tid) * 8;
        float4 a = *(const float4*)(x + i);
        float4 b = *(const float4*)(x + i + 4);
        *(uint4*)(xh + i) = make_uint4(pack_h2(a.x, a.y), pack_h2(a.z, a.w),
                                       pack_h2(b.x, b.y), pack_h2(b.z, b.w));
        return;
    }
    const float* in;  __half* out;  int R, Cc, bx, by;
    if (bid < BM_BLOCKS + X2H_BLOCKS + TQ_BLOCKS) {
        int t = bid - BM_BLOCKS - X2H_BLOCKS;
        in = wq; out = wqT; R = CDIM; Cc = QKV_N;
        bx = (t % 27) * 32; by = (t / 27) * 32;
    } else {
        int t = bid - BM_BLOCKS - X2H_BLOCKS - TQ_BLOCKS;
        in = wp; out = wpT; R = CDIM; Cc = CDIM;
        bx = (t % 9) * 32; by = (t / 9) * 32;
    }
    int xx = tid & 31, yy = tid >> 5;
#pragma unroll
    for (int j = 0; j < 4; j++)
        tt[yy + 8 * j][xx] = in[(size_t)(by + yy + 8 * j) * Cc + bx + xx];
    __syncthreads();
#pragma unroll
    for (int j = 0; j < 4; j++)
        out[(size_t)(bx + yy + 8 * j) * R + by + xx] = __float2half(tt[xx][yy + 8 * j]);
}

// ==================== GEMM1: cp.async 4-stage + ldmatrix ====================
#define G1_SMEM 71680

__global__ __launch_bounds__(256)
void gemm1_kernel(const __half* __restrict__ Aw, const __half* __restrict__ Bx,
                  __half* __restrict__ Ch, __half* __restrict__ vc) {
    extern __shared__ float smf[];
    const uint32_t smb = smem_u32_of(smf);
    const int tid = threadIdx.x, lane = tid & 31, warp = tid >> 5;
    const int qr = lane >> 2, qc = lane & 3;
    const int wm = warp & 1, wn = warp >> 1;
    const int n0 = blockIdx.x * 128;
    const int m0 = blockIdx.y * 96;
    const int bb = n0 >> 15;
    const int l0 = n0 & (L_TOT - 1);

    const int g8 = lane >> 3, lr = lane & 7;
    const int rowA = lr + (g8 & 1) * 8, colA = (g8 >> 1) * 16;
    const int rowB = lr + (g8 >> 1) * 8, colB = (g8 & 1) * 16;
    uint32_t aoff[3], boff[2];
#pragma unroll
    for (int mt = 0; mt < 3; mt++)
        aoff[mt] = (wm * 48 + mt * 16 + rowA) * 80 + colA;
#pragma unroll
    for (int p = 0; p < 2; p++)
        boff[p] = 7680 + (wn * 32 + p * 16 + rowB) * 80 + colB;

    float acc[3][4][4];
#pragma unroll
    for (int mt = 0; mt < 3; mt++)
#pragma unroll
        for (int nt = 0; nt < 4; nt++)
#pragma unroll
            for (int r = 0; r < 4; r++) acc[mt][nt][r] = 0.0f;

#define ISSUE(S, K0) do { \
    uint32_t base = smb + (S) * 17920; \
    { int r = tid >> 2, c = tid & 3; \
      CP16(base + r * 80 + c * 16, Aw + (size_t)(m0 + r) * CDIM + (K0) + c * 8); } \
    if (tid < 128) { int idx = tid + 256; \
      int r = idx >> 2, c = idx & 3; \
      CP16(base + r * 80 + c * 16, Aw + (size_t)(m0 + r) * CDIM + (K0) + c * 8); } \
    _Pragma("unroll") for (int i = 0; i < 2; i++) { \
      int idx = tid + i * 256; \
      int r = idx >> 2, c = idx & 3; \
      CP16(base + 7680 + r * 80 + c * 16, Bx + (size_t)(n0 + r) * CDIM + (K0) + c * 8); } \
    CP_COMMIT(); \
} while (0)

    ISSUE(0, 0);
    ISSUE(1, 32);
    ISSUE(2, 64);

#pragma unroll 1
    for (int ch = 0; ch < 9; ch++) {
        if (ch <= 6) { CP_WAIT2(); } else if (ch == 7) { CP_WAIT1(); } else { CP_WAIT0(); }
        __syncthreads();
        if (ch < 6) ISSUE((ch + 3) & 3, (ch + 3) * 32);

        const uint32_t sb = smb + (ch & 3) * 17920;
#pragma unroll
        for (int s = 0; s < 2; s++) {
            const int so = s * 32;
            uint32_t af[3][4], bf[2][4];
#pragma unroll
            for (int mt = 0; mt < 3; mt++)
                ldsm4(af[mt][0], af[mt][1], af[mt][2], af[mt][3], sb + aoff[mt] + so);
#pragma unroll
            for (int p = 0; p < 2; p++)
                ldsm4(bf[p][0], bf[p][1], bf[p][2], bf[p][3], sb + boff[p] + so);
#pragma unroll
            for (int mt = 0; mt < 3; mt++)
#pragma unroll
                for (int nt = 0; nt < 4; nt++)
                    mma16(acc[mt][nt], af[mt][0], af[mt][1], af[mt][2], af[mt][3],
                          bf[nt >> 1][(nt & 1) * 2], bf[nt >> 1][(nt & 1) * 2 + 1]);
        }
    }
#undef ISSUE
    __syncthreads();

    float* stg = smf;                  // [96][133]
#pragma unroll
    for (int mt = 0; mt < 3; mt++) {
        int r0 = wm * 48 + mt * 16 + qr;
#pragma unroll
        for (int nt = 0; nt < 4; nt++) {
            int c0 = wn * 32 + nt * 8 + 2 * qc;
            stg[r0 * 133 + c0]           = acc[mt][nt][0];
            stg[r0 * 133 + c0 + 1]       = acc[mt][nt][1];
            stg[(r0 + 8) * 133 + c0]     = acc[mt][nt][2];
            stg[(r0 + 8) * 133 + c0 + 1] = acc[mt][nt][3];
        }
    }
    __syncthreads();

#pragma unroll
    for (int i = 0; i < 6; i++) {
        int idx = tid + i * 256;
        int t = idx / 12, q = idx - t * 12;
        uint32_t u0 = pack_h2(stg[(q * 8 + 0) * 133 + t], stg[(q * 8 + 1) * 133 + t]);
        uint32_t u1 = pack_h2(stg[(q * 8 + 2) * 133 + t], stg[(q * 8 + 3) * 133 + t]);
        uint32_t u2 = pack_h2(stg[(q * 8 + 4) * 133 + t], stg[(q * 8 + 5) * 133 + t]);
        uint32_t u3 = pack_h2(stg[(q * 8 + 6) * 133 + t], stg[(q * 8 + 7) * 133 + t]);
        *(uint4*)(Ch + (size_t)(n0 + t) * QKV_N + m0 + q * 8) = make_uint4(u0, u1, u2, u3);
    }
    if (m0 >= 2 * CDIM) {
#pragma unroll
        for (int i = 0; i < 6; i++) {
            int idx = tid + i * 256;
            int m = idx >> 4, c8 = (idx & 15) * 8;
            uint32_t u0 = pack_h2(stg[m * 133 + c8 + 0], stg[m * 133 + c8 + 1]);
            uint32_t u1 = pack_h2(stg[m * 133 + c8 + 2], stg[m * 133 + c8 + 3]);
            uint32_t u2 = pack_h2(stg[m * 133 + c8 + 4], stg[m * 133 + c8 + 5]);
            uint32_t u3 = pack_h2(stg[m * 133 + c8 + 6], stg[m * 133 + c8 + 7]);
            *(uint4*)(vc + ((size_t)bb * CDIM + (m0 - 2 * CDIM) + m) * L_TOT + l0 + c8)
                = make_uint4(u0, u1, u2, u3);
        }
    }
}

// ==================== GEMM2: out = y @ Wp^T + lcm^T @ Wp^T + bias ====================
#define G2_STAGE 26624
#define G2_SMEM  (2 * G2_STAGE)     // 53248

__global__ __launch_bounds__(256)
void gemm2_kernel(const __half* __restrict__ Aw, const __half* __restrict__ By,
                  const __half* __restrict__ lcm, float* __restrict__ Cf,
                  const float* __restrict__ bias) {
    extern __shared__ float smf[];
    const uint32_t smb = smem_u32_of(smf);
    const int tid = threadIdx.x, lane = tid & 31, warp = tid >> 5;
    const int qr = lane >> 2, qc = lane & 3;
    const int wm = warp & 1, wn = warp >> 1;
    const int n0 = blockIdx.x * 128;
    const int m0 = blockIdx.y * 96;
    const int bb = n0 >> 15;
    const int l0 = n0 & (L_TOT - 1);

    const int g8 = lane >> 3, lr = lane & 7;
    const int rowA = lr + (g8 & 1) * 8, colA = (g8 >> 1) * 16;
    const int rowB = lr + (g8 >> 1) * 8, colB = (g8 & 1) * 16;
    uint32_t aoff[3], byoff[2], lcoff[2];
#pragma unroll
    for (int mt = 0; mt < 3; mt++)
        aoff[mt] = (wm * 48 + mt * 16 + rowA) * 80 + colA;
#pragma unroll
    for (int p = 0; p < 2; p++) {
        byoff[p] = 7680 + (wn * 32 + p * 16 + rowB) * 80 + colB;
        lcoff[p] = 17920 + ((g8 & 1) * 8 + lr) * 272
                 + (wn * 32 + p * 16 + (g8 >> 1) * 8) * 2;
    }

    float acc[3][4][4];
#pragma unroll
    for (int mt = 0; mt < 3; mt++)
#pragma unroll
        for (int nt = 0; nt < 4; nt++)
#pragma unroll
            for (int r = 0; r < 4; r++) acc[mt][nt][r] = 0.0f;

#define ISSUE2(S, K0) do { \
    uint32_t base = smb + (S) * G2_STAGE; \
    { int r = tid >> 2, c = tid & 3; \
      CP16(base + r * 80 + c * 16, Aw + (size_t)(m0 + r) * CDIM + (K0) + c * 8); } \
    if (tid < 128) { int idx = tid + 256; \
      int r = idx >> 2, c = idx & 3; \
      CP16(base + r * 80 + c * 16, Aw + (size_t)(m0 + r) * CDIM + (K0) + c * 8); } \
    _Pragma("unroll") for (int i = 0; i < 2; i++) { \
      int idx = tid + i * 256; \
      int r = idx >> 2, c = idx & 3; \
      CP16(base + 7680 + r * 80 + c * 16, By + (size_t)(n0 + r) * CDIM + (K0) + c * 8); } \
    _Pragma("unroll") for (int i = 0; i < 2; i++) { \
      int idx = tid + i * 256; \
      int r = idx >> 4, c = idx & 15; \
      CP16(base + 17920 + r * 272 + c * 16, \
           lcm + ((size_t)bb * CDIM + (K0) + r) * L_TOT + l0 + c * 8); } \
    CP_COMMIT(); \
} while (0)

    ISSUE2(0, 0);
    ISSUE2(1, 32);

#pragma unroll 1
    for (int ch = 0; ch < 9; ch++) {
        if (ch < 8) { CP_WAIT1(); } else { CP_WAIT0(); }
        __syncthreads();

        const uint32_t sb = smb + (ch & 1) * G2_STAGE;
#pragma unroll
        for (int s = 0; s < 2; s++) {
            uint32_t af[3][4], bfY[2][4], bfL[2][4];
#pragma unroll
            for (int mt = 0; mt < 3; mt++)
                ldsm4(af[mt][0], af[mt][1], af[mt][2], af[mt][3], sb + aoff[mt] + s * 32);
#pragma unroll
            for (int p = 0; p < 2; p++)
                ldsm4(bfY[p][0], bfY[p][1], bfY[p][2], bfY[p][3], sb + byoff[p] + s * 32);
#pragma unroll
            for (int p = 0; p < 2; p++)
                ldsm4t(bfL[p][0], bfL[p][1], bfL[p][2], bfL[p][3], sb + lcoff[p] + s * 4352);
#pragma unroll
            for (int mt = 0; mt < 3; mt++)
#pragma unroll
                for (int nt = 0; nt < 4; nt++) {
                    mma16(acc[mt][nt], af[mt][0], af[mt][1], af[mt][2], af[mt][3],
                          bfY[nt >> 1][(nt & 1) * 2], bfY[nt >> 1][(nt & 1) * 2 + 1]);
                    mma16(acc[mt][nt], af[mt][0], af[mt][1], af[mt][2], af[mt][3],
                          bfL[nt >> 1][(nt & 1) * 2], bfL[nt >> 1][(nt & 1) * 2 + 1]);
                }
        }

        if (ch < 7) {
            __syncthreads();
            ISSUE2(ch & 1, (ch + 2) * 32);
        }
    }
#undef ISSUE2
    __syncthreads();

    float* stg = smf;                  // [96][133]
#pragma unroll
    for (int mt = 0; mt < 3; mt++) {
        int r0 = wm * 48 + mt * 16 + qr;
#pragma unroll
        for (int nt = 0; nt < 4; nt++) {
            int c0 = wn * 32 + nt * 8 + 2 * qc;
            stg[r0 * 133 + c0]           = acc[mt][nt][0];
            stg[r0 * 133 + c0 + 1]       = acc[mt][nt][1];
            stg[(r0 + 8) * 133 + c0]     = acc[mt][nt][2];
            stg[(r0 + 8) * 133 + c0 + 1] = acc[mt][nt][3];
        }
    }
    __syncthreads();

#pragma unroll
    for (int i = 0; i < 12; i++) {
        int idx = tid + i * 256;
        int t = idx / 24, q = idx - t * 24;
        float4 o;
        o.x = stg[(q * 4 + 0) * 133 + t] + bias[m0 + q * 4 + 0];
        o.y = stg[(q * 4 + 1) * 133 + t] + bias[m0 + q * 4 + 1];
        o.z = stg[(q * 4 + 2) * 133 + t] + bias[m0 + q * 4 + 2];
        o.w = stg[(q * 4 + 3) * 133 + t] + bias[m0 + q * 4 + 3];
        *(float4*)(Cf + (size_t)(n0 + t) * CDIM + m0 + q * 4) = o;
    }
}

// ==================== fused conv + attention ====================
// Attention thread map: token = tl>>2, head = tl&3 -> 4 consecutive lanes cover
// one token's contiguous 192B branch slice (coalesced global loads and y writes).
#define CONV_BLOCKS (BATCH * CDIM * 2)        // 1152
#define ATTN_BLOCKS 6144
#define FUSE_BLOCKS (CONV_BLOCKS + ATTN_BLOCKS)

__global__ __launch_bounds__(128)
void attn_conv_kernel(const __half* __restrict__ qkv, const float* __restrict__ biasb,
                      __half* __restrict__ y, const __half* __restrict__ vc,
                      const float* __restrict__ cw, const float* __restrict__ cb,
                      __half* __restrict__ lcm) {
    __shared__ float shm[7168];
    const int tid = threadIdx.x;

    if (blockIdx.x >= CONV_BLOCKS) {
        const int abid = blockIdx.x - CONV_BLOCKS;
        const int bi = abid / 2048;
        const int rem = abid - bi * 2048;
        const int b = rem >> 10;
        const int pair = rem & 1023;
        const int Dsp = c_Dsp[bi], Hsp = c_Hsp[bi], Wsp = c_Wsp[bi];
        const int nH = RESV / Hsp, nW = RESV / Wsp;
        const int g  = tid >> 6;
        const int tl = tid & 63;
        int widx = pair * 2 + g;
        int wblk = widx % nW; int tmp = widx / nW;
        int hblk = tmp % nH;  int dblk = tmp / nH;

        const int n  = tl >> 2;   // token in window (0..15)
        const int hb = tl & 3;    // head (0..3)
        const int HW = Hsp * Wsp;
        int dd = n / HW; int r = n - dd * HW;
        int hh = r / Wsp; int ww = r - hh * Wsp;
        int l = ((dblk * Dsp + dd) * RESV + hblk * Hsp + hh) * RESV + wblk * Wsp + ww;

        size_t rowbase = ((size_t)b * L_TOT + l) * QKV_N + bi * 96 + hb * HDIM;

        float* skr = shm + g * 1792;          // [64][28], row = hb*16 + token
        float* svr = shm + 3584 + g * 1792;
        float q[HDIM];
        const float scale = 0.2041241452319315f;

        const uint4* qp = (const uint4*)(qkv + rowbase);
        const uint4* kp = (const uint4*)(qkv + rowbase + CDIM);
        const uint4* vp = (const uint4*)(qkv + rowbase + 2 * CDIM);
        const int srow = (hb * 16 + n) * 28;
#pragma unroll
        for (int j = 0; j < 3; j++) {
            uint4 uq = qp[j], uk = kp[j], uv = vp[j];
            __half2* hq = (__half2*)&uq;
            __half2* hk = (__half2*)&uk;
            __half2* hv = (__half2*)&uv;
            float kk[8], vv[8];
#pragma unroll
            for (int e = 0; e < 4; e++) {
                float2 fq = __half22float2(hq[e]);
                q[8 * j + 2 * e]     = fq.x * scale;
                q[8 * j + 2 * e + 1] = fq.y * scale;
                float2 fk = __half22float2(hk[e]);
                kk[2 * e] = fk.x; kk[2 * e + 1] = fk.y;
                float2 fv = __half22float2(hv[e]);
                vv[2 * e] = fv.x; vv[2 * e + 1] = fv.y;
            }
            *(float4*)(skr + srow + 8 * j)     = make_float4(kk[0], kk[1], kk[2], kk[3]);
            *(float4*)(skr + srow + 8 * j + 4) = make_float4(kk[4], kk[5], kk[6], kk[7]);
            *(float4*)(svr + srow + 8 * j)     = make_float4(vv[0], vv[1], vv[2], vv[3]);
            *(float4*)(svr + srow + 8 * j + 4) = make_float4(vv[4], vv[5], vv[6], vv[7]);
        }
        __syncthreads();

        const float* brow = biasb + (((size_t)bi * HB + hb) * NWIN + n) * NWIN;
        float lg[NWIN];
        float mx = -1e30f;
#pragma unroll
        for (int m = 0; m < NWIN; m++) {
            float s = brow[m];
            const float4* kr = (const float4*)(skr + (hb * 16 + m) * 28);
#pragma unroll
            for (int e4 = 0; e4 < 6; e4++) {
                float4 kk = kr[e4];
                s = fmaf(q[4 * e4 + 0], kk.x, s);
                s = fmaf(q[4 * e4 + 1], kk.y, s);
                s = fmaf(q[4 * e4 + 2], kk.z, s);
                s = fmaf(q[4 * e4 + 3], kk.w, s);
            }
            lg[m] = s;
            mx = fmaxf(mx, s);
        }
        float sum = 0.f;
#pragma unroll
        for (int m = 0; m < NWIN; m++) { lg[m] = __expf(lg[m] - mx); sum += lg[m]; }
        float inv = 1.0f / sum;

        float o[HDIM];
#pragma unroll
        for (int e = 0; e < HDIM; e++) o[e] = 0.f;
#pragma unroll
        for (int m = 0; m < NWIN; m++) {
            float w = lg[m] * inv;
            const float4* vr = (const float4*)(svr + (hb * 16 + m) * 28);
#pragma unroll
            for (int e4 = 0; e4 < 6; e4++) {
                float4 vv = vr[e4];
                o[4 * e4 + 0] = fmaf(w, vv.x, o[4 * e4 + 0]);
                o[4 * e4 + 1] = fmaf(w, vv.y, o[4 * e4 + 1]);
                o[4 * e4 + 2] = fmaf(w, vv.z, o[4 * e4 + 2]);
                o[4 * e4 + 3] = fmaf(w, vv.w, o[4 * e4 + 3]);
            }
        }

        __half* yp = y + ((size_t)b * L_TOT + l) * CDIM + bi * 96 + hb * HDIM;
#pragma unroll
        for (int j = 0; j < 3; j++) {
            uint32_t u0 = pack_h2(o[8 * j + 0], o[8 * j + 1]);
            uint32_t u1 = pack_h2(o[8 * j + 2], o[8 * j + 3]);
            uint32_t u2 = pack_h2(o[8 * j + 4], o[8 * j + 5]);
            uint32_t u3 = pack_h2(o[8 * j + 6], o[8 * j + 7]);
            *(uint4*)(yp + 8 * j) = make_uint4(u0, u1, u2, u3);
        }
        return;
    }

    // -------- depthwise 3x3x3 conv, d split in halves --------
    const int bc  = blockIdx.x >> 1;
    const int dlo = (blockIdx.x & 1) * 16;
    const int dhi = dlo + 16;
    const int c = bc % CDIM;
    const __half* src = vc + (size_t)bc * L_TOT;
    __half* dst = lcm + (size_t)bc * L_TOT;

    float wt[27];
#pragma unroll
    for (int j = 0; j < 27; j++) wt[j] = cw[c * 27 + j];
    const float bias = cb[c];

    float* sp = shm;
    const int w = tid & 31;
    const int h0 = (tid >> 5) * 8;

    for (int i = tid; i < 3 * 34 * 36; i += 128) sp[i] = 0.f;
    __syncthreads();
    {
        float* s0 = sp + (dlo % 3) * 1224;
        float* s1 = sp + ((dlo + 1) % 3) * 1224;
#pragma unroll
        for (int jh = 0; jh < 8; jh++) {
            int h = h0 + jh;
            s0[(1 + h) * 36 + 1 + w] = __half2float(src[dlo * 1024 + h * 32 + w]);
            s1[(1 + h) * 36 + 1 + w] = __half2float(src[(dlo + 1) * 1024 + h * 32 + w]);
        }
        if (dlo > 0) {
            float* sm1 = sp + ((dlo + 2) % 3) * 1224;
#pragma unroll
            for (int jh = 0; jh < 8; jh++) {
                int h = h0 + jh;
                sm1[(1 + h) * 36 + 1 + w] = __half2float(src[(dlo - 1) * 1024 + h * 32 + w]);
            }
        }
    }
    __syncthreads();

#pragma unroll 1
    for (int d = dlo; d < dhi; d++) {
        const int bm = (d + 2) % 3;
        const int b0 = d % 3;
        const int bp = (d + 1) % 3;
        float acc[8];
#pragma unroll
        for (int jh = 0; jh < 8; jh++) acc[jh] = bias;

#define TAPS(BUF, KD) { \
        const float* P = sp + (BUF) * 1224; \
        _Pragma("unroll") \
        for (int rr = 0; rr < 10; rr++) { \
            float va = P[(h0 + rr) * 36 + w], vb = P[(h0 + rr) * 36 + w + 1], \
                  vcx = P[(h0 + rr) * 36 + w + 2]; \
            _Pragma("unroll") \
            for (int jh = 0; jh < 8; jh++) { \
                int kh = rr - jh; \
                if (kh >= 0 && kh < 3) { \
                    acc[jh] = fmaf(wt[(KD)*9 + kh*3 + 0], va, \
                              fmaf(wt[(KD)*9 + kh*3 + 1], vb, \
                              fmaf(wt[(KD)*9 + kh*3 + 2], vcx, acc[jh]))); \
                } \
            } \
        } }

        if (d > 0)  TAPS(bm, 0);
        TAPS(b0, 1);
        if (d < 31) TAPS(bp, 2);
#undef TAPS

#pragma unroll
        for (int jh = 0; jh < 8; jh++)
            dst[d * 1024 + (h0 + jh) * 32 + w] = __float2half(acc[jh]);

        __syncthreads();
        if (d + 2 <= dhi && d + 2 < 32 && d < dhi - 1) {
            const __half* s2 = src + (d + 2) * 1024;
            float* spn = sp + ((d + 2) % 3) * 1224;
#pragma unroll
            for (int jh = 0; jh < 8; jh++) {
                int h = h0 + jh;
                spn[(1 + h) * 36 + 1 + w] = __half2float(s2[h * 32 + w]);
            }
        }
        __syncthreads();
    }
}

// ==================== launch ====================
extern "C" void kernel_launch(void* const* d_in, const int* in_sizes, int n_in,
                              void* d_out, int out_size) {
    const float* x      = (const float*)d_in[0];
    const float* w_qkv  = (const float*)d_in[4];
    const float* w_proj = (const float*)d_in[5];
    const float* b_proj = (const float*)d_in[6];
    const float* conv_w = (const float*)d_in[7];
    const float* conv_b = (const float*)d_in[8];
    const float* pos_w  = (const float*)d_in[9];
    const float* pos_b  = (const float*)d_in[10];
    const float* ln1g   = (const float*)d_in[11];
    const float* ln1b   = (const float*)d_in[12];
    const float* lin1w  = (const float*)d_in[13];
    const float* lin1b  = (const float*)d_in[14];
    const float* ln2g   = (const float*)d_in[15];
    const float* ln2b   = (const float*)d_in[16];
    const float* lin2w  = (const float*)d_in[17];
    const float* lin2b  = (const float*)d_in[18];
    const float* ln3g   = (const float*)d_in[19];
    const float* ln3b   = (const float*)d_in[20];
    const float* lin3w  = (const float*)d_in[21];
    const float* lin3b  = (const float*)d_in[22];
    const float* rpe    = (const float*)d_in[23];
    const int*   relidx = (const int*)d_in[24];
    float* out = (float*)d_out;

    __half *xhp, *qkvp, *yp, *vcp, *lcmp, *wqkvT, *wprojT;
    float *bp;
    cudaGetSymbolAddress((void**)&xhp,    g_xh);
    cudaGetSymbolAddress((void**)&qkvp,   g_qkv);
    cudaGetSymbolAddress((void**)&yp,     g_y);
    cudaGetSymbolAddress((void**)&bp,     g_bias);
    cudaGetSymbolAddress((void**)&vcp,    g_vc);
    cudaGetSymbolAddress((void**)&lcmp,   g_lcm);
    cudaGetSymbolAddress((void**)&wqkvT,  g_wqkvT);
    cudaGetSymbolAddress((void**)&wprojT, g_wprojT);

    cudaFuncSetAttribute(gemm1_kernel, cudaFuncAttributeMaxDynamicSharedMemorySize, G1_SMEM);
    cudaFuncSetAttribute(gemm2_kernel, cudaFuncAttributeMaxDynamicSharedMemorySize, G2_SMEM);

    // 0) fused prep: biasmlp + x->half + weight transposes
    prep_kernel<<<PREP_BLOCKS, 256>>>(x, xhp, w_qkv, wqkvT, w_proj, wprojT,
                                      rpe, pos_w, pos_b,
                                      ln1g, ln1b, lin1w, lin1b,
                                      ln2g, ln2b, lin2w, lin2b,
                                      ln3g, ln3b, lin3w, lin3b,
                                      relidx, bp);

    // 1) qkv = xh @ w_qkv  (also writes v channel-major into vc)
    gemm1_kernel<<<dim3(NROWS / 128, QKV_N / 96), 256, G1_SMEM>>>(wqkvT, xhp, qkvp, vcp);

    // 2) fused conv (front) + attention (coalesced token/head mapping)
    attn_conv_kernel<<<FUSE_BLOCKS, 128>>>(qkvp, bp, yp, vcp, conv_w, conv_b, lcmp);

    // 3) out = y @ Wp^T + lcm^T @ Wp^T + bias
    gemm2_kernel<<<dim3(NROWS / 128, CDIM / 96), 256, G2_SMEM>>>(wprojT, yp, lcmp, out, b_proj);
}

// round 14
// speedup vs baseline: 1.5600x; 1.5600x over previous
#include <cuda_runtime.h>
#include <cuda_fp16.h>
#include <math.h>
#include <stdint.h>

// ---------------- problem constants ----------------
#define RESV   32
#define L_TOT  (RESV*RESV*RESV)      // 32768
#define BATCH  2
#define CDIM   288
#define QKV_N  (3*CDIM)              // 864
#define NROWS  (BATCH*L_TOT)         // 65536
#define HB     4
#define HDIM   24
#define NWIN   16
#define TBIAS  63

// scratch (no cudaMalloc allowed) — fp16 intermediates
__device__ __half g_xh  [(size_t)NROWS * CDIM];
__device__ __half g_qkv [(size_t)NROWS * QKV_N];
__device__ __half g_y   [(size_t)NROWS * CDIM];
__device__ __half g_vc  [(size_t)BATCH * CDIM * L_TOT];  // v, channel-major
__device__ __half g_lcm [(size_t)BATCH * CDIM * L_TOT];  // conv out, channel-major
__device__ __half g_wqkvT[(size_t)QKV_N * CDIM];
__device__ __half g_wprojT[(size_t)CDIM * CDIM];
__device__ float  g_bias[3 * HB * NWIN * NWIN];

__constant__ int c_Dsp[3] = {2, 2, 2};
__constant__ int c_Hsp[3] = {2, 2, 4};
__constant__ int c_Wsp[3] = {4, 4, 2};

// ==================== helpers ====================
__device__ __forceinline__ uint32_t smem_u32_of(const void* p) {
    uint32_t a;
    asm("{ .reg .u64 t; cvta.to.shared.u64 t, %1; cvt.u32.u64 %0, t; }" : "=r"(a) : "l"(p));
    return a;
}

__device__ __forceinline__ void mma16(float* d,
                                      uint32_t a0, uint32_t a1, uint32_t a2, uint32_t a3,
                                      uint32_t b0, uint32_t b1) {
    asm volatile("mma.sync.aligned.m16n8k16.row.col.f32.f16.f16.f32 "
                 "{%0,%1,%2,%3}, {%4,%5,%6,%7}, {%8,%9}, {%0,%1,%2,%3};"
                 : "+f"(d[0]), "+f"(d[1]), "+f"(d[2]), "+f"(d[3])
                 : "r"(a0), "r"(a1), "r"(a2), "r"(a3), "r"(b0), "r"(b1));
}

__device__ __forceinline__ void ldsm4(uint32_t& r0, uint32_t& r1, uint32_t& r2, uint32_t& r3,
                                      uint32_t addr) {
    asm volatile("ldmatrix.sync.aligned.m8n8.x4.shared.b16 {%0,%1,%2,%3}, [%4];"
                 : "=r"(r0), "=r"(r1), "=r"(r2), "=r"(r3) : "r"(addr));
}

__device__ __forceinline__ void ldsm4t(uint32_t& r0, uint32_t& r1, uint32_t& r2, uint32_t& r3,
                                       uint32_t addr) {
    asm volatile("ldmatrix.sync.aligned.m8n8.x4.trans.shared.b16 {%0,%1,%2,%3}, [%4];"
                 : "=r"(r0), "=r"(r1), "=r"(r2), "=r"(r3) : "r"(addr));
}

__device__ __forceinline__ uint32_t pack_h2(float x, float y) {
    __half2 h = __floats2half2_rn(x, y);
    return *(uint32_t*)&h;
}

#define CP16(dst, src) \
    asm volatile("cp.async.cg.shared.global [%0], [%1], 16;" :: "r"(dst), "l"(src))
#define CP_COMMIT() asm volatile("cp.async.commit_group;")
#define CP_WAIT2()  asm volatile("cp.async.wait_group 2;")
#define CP_WAIT1()  asm volatile("cp.async.wait_group 1;")
#define CP_WAIT0()  asm volatile("cp.async.wait_group 0;")

// ==================== RPE-bias MLP piece ====================
__device__ __forceinline__ void ln_relu6(float* h, const float* g, const float* b) {
    float m = 0.f;
#pragma unroll
    for (int j = 0; j < 6; j++) m += h[j];
    m *= (1.0f / 6.0f);
    float v = 0.f;
#pragma unroll
    for (int j = 0; j < 6; j++) { float d = h[j] - m; v += d * d; }
    v *= (1.0f / 6.0f);
    float inv = rsqrtf(v + 1e-5f);
#pragma unroll
    for (int j = 0; j < 6; j++) {
        float t = (h[j] - m) * inv * g[j] + b[j];
        h[j] = t > 0.f ? t : 0.f;
    }
}

// ==================== fused prep: biasmlp + x->half + weight transposes ====================
#define BM_BLOCKS  3
#define X2H_BLOCKS 9216
#define TQ_BLOCKS  (27 * 9)
#define TP_BLOCKS  (9 * 9)
#define PREP_BLOCKS (BM_BLOCKS + X2H_BLOCKS + TQ_BLOCKS + TP_BLOCKS)

__global__ __launch_bounds__(256)
void prep_kernel(const float* __restrict__ x, __half* __restrict__ xh,
                 const float* __restrict__ wq, __half* __restrict__ wqT,
                 const float* __restrict__ wp, __half* __restrict__ wpT,
                 const float* __restrict__ rpe,
                 const float* __restrict__ pw, const float* __restrict__ pb,
                 const float* __restrict__ g1, const float* __restrict__ be1,
                 const float* __restrict__ w1, const float* __restrict__ b1,
                 const float* __restrict__ g2, const float* __restrict__ be2,
                 const float* __restrict__ w2, const float* __restrict__ b2,
                 const float* __restrict__ g3, const float* __restrict__ be3,
                 const float* __restrict__ w3, const float* __restrict__ b3,
                 const int* __restrict__ relidx, float* __restrict__ biasb) {
    __shared__ float tt[32][33];
    __shared__ float p[TBIAS][HB];
    const int bid = blockIdx.x, tid = threadIdx.x;

    if (bid < BM_BLOCKS) {
        const int bi = bid;
        if (tid < TBIAS) {
            float h[6], tmp[6];
            const float* r = rpe + (bi * TBIAS + tid) * 3;
            float r0 = r[0], r1 = r[1], r2 = r[2];
#pragma unroll
            for (int j = 0; j < 6; j++)
                h[j] = pb[bi * 6 + j]
                     + r0 * pw[(bi * 3 + 0) * 6 + j]
                     + r1 * pw[(bi * 3 + 1) * 6 + j]
                     + r2 * pw[(bi * 3 + 2) * 6 + j];
            ln_relu6(h, g1 + bi * 6, be1 + bi * 6);
#pragma unroll
            for (int j = 0; j < 6; j++) {
                float s = b1[bi * 6 + j];
#pragma unroll
                for (int i = 0; i < 6; i++) s += h[i] * w1[(bi * 6 + i) * 6 + j];
                tmp[j] = s;
            }
#pragma unroll
            for (int j = 0; j < 6; j++) h[j] = tmp[j];
            ln_relu6(h, g2 + bi * 6, be2 + bi * 6);
#pragma unroll
            for (int j = 0; j < 6; j++) {
                float s = b2[bi * 6 + j];
#pragma unroll
                for (int i = 0; i < 6; i++) s += h[i] * w2[(bi * 6 + i) * 6 + j];
                tmp[j] = s;
            }
#pragma unroll
            for (int j = 0; j < 6; j++) h[j] = tmp[j];
            ln_relu6(h, g3 + bi * 6, be3 + bi * 6);
#pragma unroll
            for (int j = 0; j < HB; j++) {
                float s = b3[bi * HB + j];
#pragma unroll
                for (int i = 0; i < 6; i++) s += h[i] * w3[(bi * 6 + i) * HB + j];
                p[tid][j] = s;
            }
        }
        __syncthreads();
        for (int i = tid; i < HB * NWIN * NWIN; i += blockDim.x) {
            int hb = i >> 8;
            int nm = i & 255;
            biasb[bi * (HB * NWIN * NWIN) + i] = p[relidx[bi * 256 + nm]][hb];
        }
        return;
    }

    if (bid < BM_BLOCKS + X2H_BLOCKS) {
        size_t i = ((size_t)(bid - BM_BLOCKS) * 256 + tid) * 8;
        float4 a = *(const float4*)(x + i);
        float4 b = *(const float4*)(x + i + 4);
        *(uint4*)(xh + i) = make_uint4(pack_h2(a.x, a.y), pack_h2(a.z, a.w),
                                       pack_h2(b.x, b.y), pack_h2(b.z, b.w));
        return;
    }
    const float* in;  __half* out;  int R, Cc, bx, by;
    if (bid < BM_BLOCKS + X2H_BLOCKS + TQ_BLOCKS) {
        int t = bid - BM_BLOCKS - X2H_BLOCKS;
        in = wq; out = wqT; R = CDIM; Cc = QKV_N;
        bx = (t % 27) * 32; by = (t / 27) * 32;
    } else {
        int t = bid - BM_BLOCKS - X2H_BLOCKS - TQ_BLOCKS;
        in = wp; out = wpT; R = CDIM; Cc = CDIM;
        bx = (t % 9) * 32; by = (t / 9) * 32;
    }
    int xx = tid & 31, yy = tid >> 5;
#pragma unroll
    for (int j = 0; j < 4; j++)
        tt[yy + 8 * j][xx] = in[(size_t)(by + yy + 8 * j) * Cc + bx + xx];
    __syncthreads();
#pragma unroll
    for (int j = 0; j < 4; j++)
        out[(size_t)(bx + yy + 8 * j) * R + by + xx] = __float2half(tt[xx][yy + 8 * j]);
}

// ==================== GEMM1: cp.async 4-stage + ldmatrix ====================
#define G1_SMEM 71680

__global__ __launch_bounds__(256)
void gemm1_kernel(const __half* __restrict__ Aw, const __half* __restrict__ Bx,
                  __half* __restrict__ Ch, __half* __restrict__ vc) {
    extern __shared__ float smf[];
    const uint32_t smb = smem_u32_of(smf);
    const int tid = threadIdx.x, lane = tid & 31, warp = tid >> 5;
    const int qr = lane >> 2, qc = lane & 3;
    const int wm = warp & 1, wn = warp >> 1;
    const int n0 = blockIdx.x * 128;
    const int m0 = blockIdx.y * 96;
    const int bb = n0 >> 15;
    const int l0 = n0 & (L_TOT - 1);

    const int g8 = lane >> 3, lr = lane & 7;
    const int rowA = lr + (g8 & 1) * 8, colA = (g8 >> 1) * 16;
    const int rowB = lr + (g8 >> 1) * 8, colB = (g8 & 1) * 16;
    uint32_t aoff[3], boff[2];
#pragma unroll
    for (int mt = 0; mt < 3; mt++)
        aoff[mt] = (wm * 48 + mt * 16 + rowA) * 80 + colA;
#pragma unroll
    for (int p = 0; p < 2; p++)
        boff[p] = 7680 + (wn * 32 + p * 16 + rowB) * 80 + colB;

    float acc[3][4][4];
#pragma unroll
    for (int mt = 0; mt < 3; mt++)
#pragma unroll
        for (int nt = 0; nt < 4; nt++)
#pragma unroll
            for (int r = 0; r < 4; r++) acc[mt][nt][r] = 0.0f;

#define ISSUE(S, K0) do { \
    uint32_t base = smb + (S) * 17920; \
    { int r = tid >> 2, c = tid & 3; \
      CP16(base + r * 80 + c * 16, Aw + (size_t)(m0 + r) * CDIM + (K0) + c * 8); } \
    if (tid < 128) { int idx = tid + 256; \
      int r = idx >> 2, c = idx & 3; \
      CP16(base + r * 80 + c * 16, Aw + (size_t)(m0 + r) * CDIM + (K0) + c * 8); } \
    _Pragma("unroll") for (int i = 0; i < 2; i++) { \
      int idx = tid + i * 256; \
      int r = idx >> 2, c = idx & 3; \
      CP16(base + 7680 + r * 80 + c * 16, Bx + (size_t)(n0 + r) * CDIM + (K0) + c * 8); } \
    CP_COMMIT(); \
} while (0)

    ISSUE(0, 0);
    ISSUE(1, 32);
    ISSUE(2, 64);

#pragma unroll 1
    for (int ch = 0; ch < 9; ch++) {
        if (ch <= 6) { CP_WAIT2(); } else if (ch == 7) { CP_WAIT1(); } else { CP_WAIT0(); }
        __syncthreads();
        if (ch < 6) ISSUE((ch + 3) & 3, (ch + 3) * 32);

        const uint32_t sb = smb + (ch & 3) * 17920;
#pragma unroll
        for (int s = 0; s < 2; s++) {
            const int so = s * 32;
            uint32_t af[3][4], bf[2][4];
#pragma unroll
            for (int mt = 0; mt < 3; mt++)
                ldsm4(af[mt][0], af[mt][1], af[mt][2], af[mt][3], sb + aoff[mt] + so);
#pragma unroll
            for (int p = 0; p < 2; p++)
                ldsm4(bf[p][0], bf[p][1], bf[p][2], bf[p][3], sb + boff[p] + so);
#pragma unroll
            for (int mt = 0; mt < 3; mt++)
#pragma unroll
                for (int nt = 0; nt < 4; nt++)
                    mma16(acc[mt][nt], af[mt][0], af[mt][1], af[mt][2], af[mt][3],
                          bf[nt >> 1][(nt & 1) * 2], bf[nt >> 1][(nt & 1) * 2 + 1]);
        }
    }
#undef ISSUE
    __syncthreads();

    float* stg = smf;                  // [96][133]
#pragma unroll
    for (int mt = 0; mt < 3; mt++) {
        int r0 = wm * 48 + mt * 16 + qr;
#pragma unroll
        for (int nt = 0; nt < 4; nt++) {
            int c0 = wn * 32 + nt * 8 + 2 * qc;
            stg[r0 * 133 + c0]           = acc[mt][nt][0];
            stg[r0 * 133 + c0 + 1]       = acc[mt][nt][1];
            stg[(r0 + 8) * 133 + c0]     = acc[mt][nt][2];
            stg[(r0 + 8) * 133 + c0 + 1] = acc[mt][nt][3];
        }
    }
    __syncthreads();

#pragma unroll
    for (int i = 0; i < 6; i++) {
        int idx = tid + i * 256;
        int t = idx / 12, q = idx - t * 12;
        uint32_t u0 = pack_h2(stg[(q * 8 + 0) * 133 + t], stg[(q * 8 + 1) * 133 + t]);
        uint32_t u1 = pack_h2(stg[(q * 8 + 2) * 133 + t], stg[(q * 8 + 3) * 133 + t]);
        uint32_t u2 = pack_h2(stg[(q * 8 + 4) * 133 + t], stg[(q * 8 + 5) * 133 + t]);
        uint32_t u3 = pack_h2(stg[(q * 8 + 6) * 133 + t], stg[(q * 8 + 7) * 133 + t]);
        *(uint4*)(Ch + (size_t)(n0 + t) * QKV_N + m0 + q * 8) = make_uint4(u0, u1, u2, u3);
    }
    if (m0 >= 2 * CDIM) {
#pragma unroll
        for (int i = 0; i < 6; i++) {
            int idx = tid + i * 256;
            int m = idx >> 4, c8 = (idx & 15) * 8;
            uint32_t u0 = pack_h2(stg[m * 133 + c8 + 0], stg[m * 133 + c8 + 1]);
            uint32_t u1 = pack_h2(stg[m * 133 + c8 + 2], stg[m * 133 + c8 + 3]);
            uint32_t u2 = pack_h2(stg[m * 133 + c8 + 4], stg[m * 133 + c8 + 5]);
            uint32_t u3 = pack_h2(stg[m * 133 + c8 + 6], stg[m * 133 + c8 + 7]);
            *(uint4*)(vc + ((size_t)bb * CDIM + (m0 - 2 * CDIM) + m) * L_TOT + l0 + c8)
                = make_uint4(u0, u1, u2, u3);
        }
    }
}

// ==================== GEMM2: out = y @ Wp^T + lcm^T @ Wp^T + bias ====================
#define G2_STAGE 26624
#define G2_SMEM  (2 * G2_STAGE)     // 53248

__global__ __launch_bounds__(256)
void gemm2_kernel(const __half* __restrict__ Aw, const __half* __restrict__ By,
                  const __half* __restrict__ lcm, float* __restrict__ Cf,
                  const float* __restrict__ bias) {
    extern __shared__ float smf[];
    const uint32_t smb = smem_u32_of(smf);
    const int tid = threadIdx.x, lane = tid & 31, warp = tid >> 5;
    const int qr = lane >> 2, qc = lane & 3;
    const int wm = warp & 1, wn = warp >> 1;
    const int n0 = blockIdx.x * 128;
    const int m0 = blockIdx.y * 96;
    const int bb = n0 >> 15;
    const int l0 = n0 & (L_TOT - 1);

    const int g8 = lane >> 3, lr = lane & 7;
    const int rowA = lr + (g8 & 1) * 8, colA = (g8 >> 1) * 16;
    const int rowB = lr + (g8 >> 1) * 8, colB = (g8 & 1) * 16;
    uint32_t aoff[3], byoff[2], lcoff[2];
#pragma unroll
    for (int mt = 0; mt < 3; mt++)
        aoff[mt] = (wm * 48 + mt * 16 + rowA) * 80 + colA;
#pragma unroll
    for (int p = 0; p < 2; p++) {
        byoff[p] = 7680 + (wn * 32 + p * 16 + rowB) * 80 + colB;
        lcoff[p] = 17920 + ((g8 & 1) * 8 + lr) * 272
                 + (wn * 32 + p * 16 + (g8 >> 1) * 8) * 2;
    }

    float acc[3][4][4];
#pragma unroll
    for (int mt = 0; mt < 3; mt++)
#pragma unroll
        for (int nt = 0; nt < 4; nt++)
#pragma unroll
            for (int r = 0; r < 4; r++) acc[mt][nt][r] = 0.0f;

#define ISSUE2(S, K0) do { \
    uint32_t base = smb + (S) * G2_STAGE; \
    { int r = tid >> 2, c = tid & 3; \
      CP16(base + r * 80 + c * 16, Aw + (size_t)(m0 + r) * CDIM + (K0) + c * 8); } \
    if (tid < 128) { int idx = tid + 256; \
      int r = idx >> 2, c = idx & 3; \
      CP16(base + r * 80 + c * 16, Aw + (size_t)(m0 + r) * CDIM + (K0) + c * 8); } \
    _Pragma("unroll") for (int i = 0; i < 2; i++) { \
      int idx = tid + i * 256; \
      int r = idx >> 2, c = idx & 3; \
      CP16(base + 7680 + r * 80 + c * 16, By + (size_t)(n0 + r) * CDIM + (K0) + c * 8); } \
    _Pragma("unroll") for (int i = 0; i < 2; i++) { \
      int idx = tid + i * 256; \
      int r = idx >> 4, c = idx & 15; \
      CP16(base + 17920 + r * 272 + c * 16, \
           lcm + ((size_t)bb * CDIM + (K0) + r) * L_TOT + l0 + c * 8); } \
    CP_COMMIT(); \
} while (0)

    ISSUE2(0, 0);
    ISSUE2(1, 32);

#pragma unroll 1
    for (int ch = 0; ch < 9; ch++) {
        if (ch < 8) { CP_WAIT1(); } else { CP_WAIT0(); }
        __syncthreads();

        const uint32_t sb = smb + (ch & 1) * G2_STAGE;
#pragma unroll
        for (int s = 0; s < 2; s++) {
            uint32_t af[3][4], bfY[2][4], bfL[2][4];
#pragma unroll
            for (int mt = 0; mt < 3; mt++)
                ldsm4(af[mt][0], af[mt][1], af[mt][2], af[mt][3], sb + aoff[mt] + s * 32);
#pragma unroll
            for (int p = 0; p < 2; p++)
                ldsm4(bfY[p][0], bfY[p][1], bfY[p][2], bfY[p][3], sb + byoff[p] + s * 32);
#pragma unroll
            for (int p = 0; p < 2; p++)
                ldsm4t(bfL[p][0], bfL[p][1], bfL[p][2], bfL[p][3], sb + lcoff[p] + s * 4352);
#pragma unroll
            for (int mt = 0; mt < 3; mt++)
#pragma unroll
                for (int nt = 0; nt < 4; nt++) {
                    mma16(acc[mt][nt], af[mt][0], af[mt][1], af[mt][2], af[mt][3],
                          bfY[nt >> 1][(nt & 1) * 2], bfY[nt >> 1][(nt & 1) * 2 + 1]);
                    mma16(acc[mt][nt], af[mt][0], af[mt][1], af[mt][2], af[mt][3],
                          bfL[nt >> 1][(nt & 1) * 2], bfL[nt >> 1][(nt & 1) * 2 + 1]);
                }
        }

        if (ch < 7) {
            __syncthreads();
            ISSUE2(ch & 1, (ch + 2) * 32);
        }
    }
#undef ISSUE2
    __syncthreads();

    float* stg = smf;                  // [96][133]
#pragma unroll
    for (int mt = 0; mt < 3; mt++) {
        int r0 = wm * 48 + mt * 16 + qr;
#pragma unroll
        for (int nt = 0; nt < 4; nt++) {
            int c0 = wn * 32 + nt * 8 + 2 * qc;
            stg[r0 * 133 + c0]           = acc[mt][nt][0];
            stg[r0 * 133 + c0 + 1]       = acc[mt][nt][1];
            stg[(r0 + 8) * 133 + c0]     = acc[mt][nt][2];
            stg[(r0 + 8) * 133 + c0 + 1] = acc[mt][nt][3];
        }
    }
    __syncthreads();

#pragma unroll
    for (int i = 0; i < 12; i++) {
        int idx = tid + i * 256;
        int t = idx / 24, q = idx - t * 24;
        float4 o;
        o.x = stg[(q * 4 + 0) * 133 + t] + bias[m0 + q * 4 + 0];
        o.y = stg[(q * 4 + 1) * 133 + t] + bias[m0 + q * 4 + 1];
        o.z = stg[(q * 4 + 2) * 133 + t] + bias[m0 + q * 4 + 2];
        o.w = stg[(q * 4 + 3) * 133 + t] + bias[m0 + q * 4 + 3];
        *(float4*)(Cf + (size_t)(n0 + t) * CDIM + m0 + q * 4) = o;
    }
}

// ==================== fused conv + attention ====================
// Attention smem rows: SROW(hb,n) = hb*452 + n*28 (16B skew per head group
// -> the 2 head groups of a warp read disjoint bank ranges; float4-aligned).
#define CONV_BLOCKS (BATCH * CDIM * 2)        // 1152
#define ATTN_BLOCKS 6144
#define FUSE_BLOCKS (CONV_BLOCKS + ATTN_BLOCKS)
#define SROW(hbv, nv) ((hbv) * 452 + (nv) * 28)

__global__ __launch_bounds__(128)
void attn_conv_kernel(const __half* __restrict__ qkv, const float* __restrict__ biasb,
                      __half* __restrict__ y, const __half* __restrict__ vc,
                      const float* __restrict__ cw, const float* __restrict__ cb,
                      __half* __restrict__ lcm) {
    __shared__ float shm[7232];
    const int tid = threadIdx.x;

    if (blockIdx.x >= CONV_BLOCKS) {
        const int abid = blockIdx.x - CONV_BLOCKS;
        const int bi = abid / 2048;
        const int rem = abid - bi * 2048;
        const int b = rem >> 10;
        const int pair = rem & 1023;
        const int Dsp = c_Dsp[bi], Hsp = c_Hsp[bi], Wsp = c_Wsp[bi];
        const int nH = RESV / Hsp, nW = RESV / Wsp;
        const int g  = tid >> 6;
        const int tl = tid & 63;
        int widx = pair * 2 + g;
        int wblk = widx % nW; int tmp = widx / nW;
        int hblk = tmp % nH;  int dblk = tmp / nH;

        const int hb = tl >> 4;
        const int n  = tl & 15;
        const int HW = Hsp * Wsp;
        int dd = n / HW; int r = n - dd * HW;
        int hh = r / Wsp; int ww = r - hh * Wsp;
        int l = ((dblk * Dsp + dd) * RESV + hblk * Hsp + hh) * RESV + wblk * Wsp + ww;

        size_t rowbase = ((size_t)b * L_TOT + l) * QKV_N + bi * 96 + hb * HDIM;

        float* skr = shm + g * 1808;          // [4 groups][16 rows] stride 28, skew 4
        float* svr = shm + 3616 + g * 1808;
        float q[HDIM];
        const float scale = 0.2041241452319315f;

        const uint4* qp = (const uint4*)(qkv + rowbase);
        const uint4* kp = (const uint4*)(qkv + rowbase + CDIM);
        const uint4* vp = (const uint4*)(qkv + rowbase + 2 * CDIM);
        const int srow = SROW(hb, n);
#pragma unroll
        for (int j = 0; j < 3; j++) {
            uint4 uq = qp[j], uk = kp[j], uv = vp[j];
            __half2* hq = (__half2*)&uq;
            __half2* hk = (__half2*)&uk;
            __half2* hv = (__half2*)&uv;
            float kk[8], vv[8];
#pragma unroll
            for (int e = 0; e < 4; e++) {
                float2 fq = __half22float2(hq[e]);
                q[8 * j + 2 * e]     = fq.x * scale;
                q[8 * j + 2 * e + 1] = fq.y * scale;
                float2 fk = __half22float2(hk[e]);
                kk[2 * e] = fk.x; kk[2 * e + 1] = fk.y;
                float2 fv = __half22float2(hv[e]);
                vv[2 * e] = fv.x; vv[2 * e + 1] = fv.y;
            }
            *(float4*)(skr + srow + 8 * j)     = make_float4(kk[0], kk[1], kk[2], kk[3]);
            *(float4*)(skr + srow + 8 * j + 4) = make_float4(kk[4], kk[5], kk[6], kk[7]);
            *(float4*)(svr + srow + 8 * j)     = make_float4(vv[0], vv[1], vv[2], vv[3]);
            *(float4*)(svr + srow + 8 * j + 4) = make_float4(vv[4], vv[5], vv[6], vv[7]);
        }
        __syncthreads();

        const float* brow = biasb + (((size_t)bi * HB + hb) * NWIN + n) * NWIN;
        float lg[NWIN];
        float mx = -1e30f;
#pragma unroll
        for (int m = 0; m < NWIN; m++) {
            float s = brow[m];
            const float4* kr = (const float4*)(skr + SROW(hb, m));
#pragma unroll
            for (int e4 = 0; e4 < 6; e4++) {
                float4 kk = kr[e4];
                s = fmaf(q[4 * e4 + 0], kk.x, s);
                s = fmaf(q[4 * e4 + 1], kk.y, s);
                s = fmaf(q[4 * e4 + 2], kk.z, s);
                s = fmaf(q[4 * e4 + 3], kk.w, s);
            }
            lg[m] = s;
            mx = fmaxf(mx, s);
        }
        float sum = 0.f;
#pragma unroll
        for (int m = 0; m < NWIN; m++) { lg[m] = __expf(lg[m] - mx); sum += lg[m]; }
        float inv = 1.0f / sum;

        float o[HDIM];
#pragma unroll
        for (int e = 0; e < HDIM; e++) o[e] = 0.f;
#pragma unroll
        for (int m = 0; m < NWIN; m++) {
            float w = lg[m] * inv;
            const float4* vr = (const float4*)(svr + SROW(hb, m));
#pragma unroll
            for (int e4 = 0; e4 < 6; e4++) {
                float4 vv = vr[e4];
                o[4 * e4 + 0] = fmaf(w, vv.x, o[4 * e4 + 0]);
                o[4 * e4 + 1] = fmaf(w, vv.y, o[4 * e4 + 1]);
                o[4 * e4 + 2] = fmaf(w, vv.z, o[4 * e4 + 2]);
                o[4 * e4 + 3] = fmaf(w, vv.w, o[4 * e4 + 3]);
            }
        }

        __half* yp = y + ((size_t)b * L_TOT + l) * CDIM + bi * 96 + hb * HDIM;
#pragma unroll
        for (int j = 0; j < 3; j++) {
            uint32_t u0 = pack_h2(o[8 * j + 0], o[8 * j + 1]);
            uint32_t u1 = pack_h2(o[8 * j + 2], o[8 * j + 3]);
            uint32_t u2 = pack_h2(o[8 * j + 4], o[8 * j + 5]);
            uint32_t u3 = pack_h2(o[8 * j + 6], o[8 * j + 7]);
            *(uint4*)(yp + 8 * j) = make_uint4(u0, u1, u2, u3);
        }
        return;
    }

    // -------- depthwise 3x3x3 conv, d split in halves --------
    const int bc  = blockIdx.x >> 1;
    const int dlo = (blockIdx.x & 1) * 16;
    const int dhi = dlo + 16;
    const int c = bc % CDIM;
    const __half* src = vc + (size_t)bc * L_TOT;
    __half* dst = lcm + (size_t)bc * L_TOT;

    float wt[27];
#pragma unroll
    for (int j = 0; j < 27; j++) wt[j] = cw[c * 27 + j];
    const float bias = cb[c];

    float* sp = shm;
    const int w = tid & 31;
    const int h0 = (tid >> 5) * 8;

    for (int i = tid; i < 3 * 34 * 36; i += 128) sp[i] = 0.f;
    __syncthreads();
    {
        float* s0 = sp + (dlo % 3) * 1224;
        float* s1 = sp + ((dlo + 1) % 3) * 1224;
#pragma unroll
        for (int jh = 0; jh < 8; jh++) {
            int h = h0 + jh;
            s0[(1 + h) * 36 + 1 + w] = __half2float(src[dlo * 1024 + h * 32 + w]);
            s1[(1 + h) * 36 + 1 + w] = __half2float(src[(dlo + 1) * 1024 + h * 32 + w]);
        }
        if (dlo > 0) {
            float* sm1 = sp + ((dlo + 2) % 3) * 1224;
#pragma unroll
            for (int jh = 0; jh < 8; jh++) {
                int h = h0 + jh;
                sm1[(1 + h) * 36 + 1 + w] = __half2float(src[(dlo - 1) * 1024 + h * 32 + w]);
            }
        }
    }
    __syncthreads();

#pragma unroll 1
    for (int d = dlo; d < dhi; d++) {
        const int bm = (d + 2) % 3;
        const int b0 = d % 3;
        const int bp = (d + 1) % 3;
        float acc[8];
#pragma unroll
        for (int jh = 0; jh < 8; jh++) acc[jh] = bias;

#define TAPS(BUF, KD) { \
        const float* P = sp + (BUF) * 1224; \
        _Pragma("unroll") \
        for (int rr = 0; rr < 10; rr++) { \
            float va = P[(h0 + rr) * 36 + w], vb = P[(h0 + rr) * 36 + w + 1], \
                  vcx = P[(h0 + rr) * 36 + w + 2]; \
            _Pragma("unroll") \
            for (int jh = 0; jh < 8; jh++) { \
                int kh = rr - jh; \
                if (kh >= 0 && kh < 3) { \
                    acc[jh] = fmaf(wt[(KD)*9 + kh*3 + 0], va, \
                              fmaf(wt[(KD)*9 + kh*3 + 1], vb, \
                              fmaf(wt[(KD)*9 + kh*3 + 2], vcx, acc[jh]))); \
                } \
            } \
        } }

        if (d > 0)  TAPS(bm, 0);
        TAPS(b0, 1);
        if (d < 31) TAPS(bp, 2);
#undef TAPS

#pragma unroll
        for (int jh = 0; jh < 8; jh++)
            dst[d * 1024 + (h0 + jh) * 32 + w] = __float2half(acc[jh]);

        __syncthreads();
        if (d + 2 <= dhi && d + 2 < 32 && d < dhi - 1) {
            const __half* s2 = src + (d + 2) * 1024;
            float* spn = sp + ((d + 2) % 3) * 1224;
#pragma unroll
            for (int jh = 0; jh < 8; jh++) {
                int h = h0 + jh;
                spn[(1 + h) * 36 + 1 + w] = __half2float(s2[h * 32 + w]);
            }
        }
        __syncthreads();
    }
}

// ==================== launch ====================
extern "C" void kernel_launch(void* const* d_in, const int* in_sizes, int n_in,
                              void* d_out, int out_size) {
    const float* x      = (const float*)d_in[0];
    const float* w_qkv  = (const float*)d_in[4];
    const float* w_proj = (const float*)d_in[5];
    const float* b_proj = (const float*)d_in[6];
    const float* conv_w = (const float*)d_in[7];
    const float* conv_b = (const float*)d_in[8];
    const float* pos_w  = (const float*)d_in[9];
    const float* pos_b  = (const float*)d_in[10];
    const float* ln1g   = (const float*)d_in[11];
    const float* ln1b   = (const float*)d_in[12];
    const float* lin1w  = (const float*)d_in[13];
    const float* lin1b  = (const float*)d_in[14];
    const float* ln2g   = (const float*)d_in[15];
    const float* ln2b   = (const float*)d_in[16];
    const float* lin2w  = (const float*)d_in[17];
    const float* lin2b  = (const float*)d_in[18];
    const float* ln3g   = (const float*)d_in[19];
    const float* ln3b   = (const float*)d_in[20];
    const float* lin3w  = (const float*)d_in[21];
    const float* lin3b  = (const float*)d_in[22];
    const float* rpe    = (const float*)d_in[23];
    const int*   relidx = (const int*)d_in[24];
    float* out = (float*)d_out;

    __half *xhp, *qkvp, *yp, *vcp, *lcmp, *wqkvT, *wprojT;
    float *bp;
    cudaGetSymbolAddress((void**)&xhp,    g_xh);
    cudaGetSymbolAddress((void**)&qkvp,   g_qkv);
    cudaGetSymbolAddress((void**)&yp,     g_y);
    cudaGetSymbolAddress((void**)&bp,     g_bias);
    cudaGetSymbolAddress((void**)&vcp,    g_vc);
    cudaGetSymbolAddress((void**)&lcmp,   g_lcm);
    cudaGetSymbolAddress((void**)&wqkvT,  g_wqkvT);
    cudaGetSymbolAddress((void**)&wprojT, g_wprojT);

    cudaFuncSetAttribute(gemm1_kernel, cudaFuncAttributeMaxDynamicSharedMemorySize, G1_SMEM);
    cudaFuncSetAttribute(gemm2_kernel, cudaFuncAttributeMaxDynamicSharedMemorySize, G2_SMEM);

    // 0) fused prep: biasmlp + x->half + weight transposes
    prep_kernel<<<PREP_BLOCKS, 256>>>(x, xhp, w_qkv, wqkvT, w_proj, wprojT,
                                      rpe, pos_w, pos_b,
                                      ln1g, ln1b, lin1w, lin1b,
                                      ln2g, ln2b, lin2w, lin2b,
                                      ln3g, ln3b, lin3w, lin3b,
                                      relidx, bp);

    // 1) qkv = xh @ w_qkv  (also writes v channel-major into vc)
    gemm1_kernel<<<dim3(NROWS / 128, QKV_N / 96), 256, G1_SMEM>>>(wqkvT, xhp, qkvp, vcp);

    // 2) fused conv (front) + attention (R12 mapping + bank-skewed smem rows)
    attn_conv_kernel<<<FUSE_BLOCKS, 128>>>(qkvp, bp, yp, vcp, conv_w, conv_b, lcmp);

    // 3) out = y @ Wp^T + lcm^T @ Wp^T + bias
    gemm2_kernel<<<dim3(NROWS / 128, CDIM / 96), 256, G2_SMEM>>>(wprojT, yp, lcmp, out, b_proj);
}

// round 15
// speedup vs baseline: 1.5624x; 1.0016x over previous
#include <cuda_runtime.h>
#include <cuda_fp16.h>
#include <math.h>
#include <stdint.h>

// ---------------- problem constants ----------------
#define RESV   32
#define L_TOT  (RESV*RESV*RESV)      // 32768
#define BATCH  2
#define CDIM   288
#define QKV_N  (3*CDIM)              // 864
#define NROWS  (BATCH*L_TOT)         // 65536
#define HB     4
#define HDIM   24
#define NWIN   16
#define TBIAS  63

// scratch (no cudaMalloc allowed) — fp16 intermediates
__device__ __half g_xh  [(size_t)NROWS * CDIM];
__device__ __half g_qkv [(size_t)NROWS * QKV_N];
__device__ __half g_y   [(size_t)NROWS * CDIM];
__device__ __half g_vc  [(size_t)BATCH * CDIM * L_TOT];  // v, channel-major
__device__ __half g_lcm [(size_t)BATCH * CDIM * L_TOT];  // conv out, channel-major
__device__ __half g_wqkvT[(size_t)QKV_N * CDIM];
__device__ __half g_wprojT[(size_t)CDIM * CDIM];
__device__ float  g_bias[3 * HB * NWIN * NWIN];

__constant__ int c_Dsp[3] = {2, 2, 2};
__constant__ int c_Hsp[3] = {2, 2, 4};
__constant__ int c_Wsp[3] = {4, 4, 2};

// ==================== helpers ====================
__device__ __forceinline__ uint32_t smem_u32_of(const void* p) {
    uint32_t a;
    asm("{ .reg .u64 t; cvta.to.shared.u64 t, %1; cvt.u32.u64 %0, t; }" : "=r"(a) : "l"(p));
    return a;
}

__device__ __forceinline__ void mma16(float* d,
                                      uint32_t a0, uint32_t a1, uint32_t a2, uint32_t a3,
                                      uint32_t b0, uint32_t b1) {
    asm volatile("mma.sync.aligned.m16n8k16.row.col.f32.f16.f16.f32 "
                 "{%0,%1,%2,%3}, {%4,%5,%6,%7}, {%8,%9}, {%0,%1,%2,%3};"
                 : "+f"(d[0]), "+f"(d[1]), "+f"(d[2]), "+f"(d[3])
                 : "r"(a0), "r"(a1), "r"(a2), "r"(a3), "r"(b0), "r"(b1));
}

__device__ __forceinline__ void ldsm4(uint32_t& r0, uint32_t& r1, uint32_t& r2, uint32_t& r3,
                                      uint32_t addr) {
    asm volatile("ldmatrix.sync.aligned.m8n8.x4.shared.b16 {%0,%1,%2,%3}, [%4];"
                 : "=r"(r0), "=r"(r1), "=r"(r2), "=r"(r3) : "r"(addr));
}

__device__ __forceinline__ void ldsm4t(uint32_t& r0, uint32_t& r1, uint32_t& r2, uint32_t& r3,
                                       uint32_t addr) {
    asm volatile("ldmatrix.sync.aligned.m8n8.x4.trans.shared.b16 {%0,%1,%2,%3}, [%4];"
                 : "=r"(r0), "=r"(r1), "=r"(r2), "=r"(r3) : "r"(addr));
}

__device__ __forceinline__ uint32_t pack_h2(float x, float y) {
    __half2 h = __floats2half2_rn(x, y);
    return *(uint32_t*)&h;
}

#define CP16(dst, src) \
    asm volatile("cp.async.cg.shared.global [%0], [%1], 16;" :: "r"(dst), "l"(src))
#define CP_COMMIT() asm volatile("cp.async.commit_group;")
#define CP_WAIT2()  asm volatile("cp.async.wait_group 2;")
#define CP_WAIT1()  asm volatile("cp.async.wait_group 1;")
#define CP_WAIT0()  asm volatile("cp.async.wait_group 0;")

// ==================== RPE-bias MLP piece ====================
__device__ __forceinline__ void ln_relu6(float* h, const float* g, const float* b) {
    float m = 0.f;
#pragma unroll
    for (int j = 0; j < 6; j++) m += h[j];
    m *= (1.0f / 6.0f);
    float v = 0.f;
#pragma unroll
    for (int j = 0; j < 6; j++) { float d = h[j] - m; v += d * d; }
    v *= (1.0f / 6.0f);
    float inv = rsqrtf(v + 1e-5f);
#pragma unroll
    for (int j = 0; j < 6; j++) {
        float t = (h[j] - m) * inv * g[j] + b[j];
        h[j] = t > 0.f ? t : 0.f;
    }
}

// ==================== fused prep: biasmlp + x->half + weight transposes ====================
#define BM_BLOCKS  3
#define X2H_BLOCKS 9216
#define TQ_BLOCKS  (27 * 9)
#define TP_BLOCKS  (9 * 9)
#define PREP_BLOCKS (BM_BLOCKS + X2H_BLOCKS + TQ_BLOCKS + TP_BLOCKS)

__global__ __launch_bounds__(256)
void prep_kernel(const float* __restrict__ x, __half* __restrict__ xh,
                 const float* __restrict__ wq, __half* __restrict__ wqT,
                 const float* __restrict__ wp, __half* __restrict__ wpT,
                 const float* __restrict__ rpe,
                 const float* __restrict__ pw, const float* __restrict__ pb,
                 const float* __restrict__ g1, const float* __restrict__ be1,
                 const float* __restrict__ w1, const float* __restrict__ b1,
                 const float* __restrict__ g2, const float* __restrict__ be2,
                 const float* __restrict__ w2, const float* __restrict__ b2,
                 const float* __restrict__ g3, const float* __restrict__ be3,
                 const float* __restrict__ w3, const float* __restrict__ b3,
                 const int* __restrict__ relidx, float* __restrict__ biasb) {
    __shared__ float tt[32][33];
    __shared__ float p[TBIAS][HB];
    const int bid = blockIdx.x, tid = threadIdx.x;

    if (bid < BM_BLOCKS) {
        const int bi = bid;
        if (tid < TBIAS) {
            float h[6], tmp[6];
            const float* r = rpe + (bi * TBIAS + tid) * 3;
            float r0 = r[0], r1 = r[1], r2 = r[2];
#pragma unroll
            for (int j = 0; j < 6; j++)
                h[j] = pb[bi * 6 + j]
                     + r0 * pw[(bi * 3 + 0) * 6 + j]
                     + r1 * pw[(bi * 3 + 1) * 6 + j]
                     + r2 * pw[(bi * 3 + 2) * 6 + j];
            ln_relu6(h, g1 + bi * 6, be1 + bi * 6);
#pragma unroll
            for (int j = 0; j < 6; j++) {
                float s = b1[bi * 6 + j];
#pragma unroll
                for (int i = 0; i < 6; i++) s += h[i] * w1[(bi * 6 + i) * 6 + j];
                tmp[j] = s;
            }
#pragma unroll
            for (int j = 0; j < 6; j++) h[j] = tmp[j];
            ln_relu6(h, g2 + bi * 6, be2 + bi * 6);
#pragma unroll
            for (int j = 0; j < 6; j++) {
                float s = b2[bi * 6 + j];
#pragma unroll
                for (int i = 0; i < 6; i++) s += h[i] * w2[(bi * 6 + i) * 6 + j];
                tmp[j] = s;
            }
#pragma unroll
            for (int j = 0; j < 6; j++) h[j] = tmp[j];
            ln_relu6(h, g3 + bi * 6, be3 + bi * 6);
#pragma unroll
            for (int j = 0; j < HB; j++) {
                float s = b3[bi * HB + j];
#pragma unroll
                for (int i = 0; i < 6; i++) s += h[i] * w3[(bi * 6 + i) * HB + j];
                p[tid][j] = s;
            }
        }
        __syncthreads();
        for (int i = tid; i < HB * NWIN * NWIN; i += blockDim.x) {
            int hb = i >> 8;
            int nm = i & 255;
            biasb[bi * (HB * NWIN * NWIN) + i] = p[relidx[bi * 256 + nm]][hb];
        }
        return;
    }

    if (bid < BM_BLOCKS + X2H_BLOCKS) {
        size_t i = ((size_t)(bid - BM_BLOCKS) * 256 + tid) * 8;
        float4 a = *(const float4*)(x + i);
        float4 b = *(const float4*)(x + i + 4);
        *(uint4*)(xh + i) = make_uint4(pack_h2(a.x, a.y), pack_h2(a.z, a.w),
                                       pack_h2(b.x, b.y), pack_h2(b.z, b.w));
        return;
    }
    const float* in;  __half* out;  int R, Cc, bx, by;
    if (bid < BM_BLOCKS + X2H_BLOCKS + TQ_BLOCKS) {
        int t = bid - BM_BLOCKS - X2H_BLOCKS;
        in = wq; out = wqT; R = CDIM; Cc = QKV_N;
        bx = (t % 27) * 32; by = (t / 27) * 32;
    } else {
        int t = bid - BM_BLOCKS - X2H_BLOCKS - TQ_BLOCKS;
        in = wp; out = wpT; R = CDIM; Cc = CDIM;
        bx = (t % 9) * 32; by = (t / 9) * 32;
    }
    int xx = tid & 31, yy = tid >> 5;
#pragma unroll
    for (int j = 0; j < 4; j++)
        tt[yy + 8 * j][xx] = in[(size_t)(by + yy + 8 * j) * Cc + bx + xx];
    __syncthreads();
#pragma unroll
    for (int j = 0; j < 4; j++)
        out[(size_t)(bx + yy + 8 * j) * R + by + xx] = __float2half(tt[xx][yy + 8 * j]);
}

// ==================== GEMM1: cp.async 4-stage + ldmatrix ====================
#define G1_SMEM 71680

__global__ __launch_bounds__(256)
void gemm1_kernel(const __half* __restrict__ Aw, const __half* __restrict__ Bx,
                  __half* __restrict__ Ch, __half* __restrict__ vc) {
    extern __shared__ float smf[];
    const uint32_t smb = smem_u32_of(smf);
    const int tid = threadIdx.x, lane = tid & 31, warp = tid >> 5;
    const int qr = lane >> 2, qc = lane & 3;
    const int wm = warp & 1, wn = warp >> 1;
    const int n0 = blockIdx.x * 128;
    const int m0 = blockIdx.y * 96;
    const int bb = n0 >> 15;
    const int l0 = n0 & (L_TOT - 1);

    const int g8 = lane >> 3, lr = lane & 7;
    const int rowA = lr + (g8 & 1) * 8, colA = (g8 >> 1) * 16;
    const int rowB = lr + (g8 >> 1) * 8, colB = (g8 & 1) * 16;
    uint32_t aoff[3], boff[2];
#pragma unroll
    for (int mt = 0; mt < 3; mt++)
        aoff[mt] = (wm * 48 + mt * 16 + rowA) * 80 + colA;
#pragma unroll
    for (int p = 0; p < 2; p++)
        boff[p] = 7680 + (wn * 32 + p * 16 + rowB) * 80 + colB;

    float acc[3][4][4];
#pragma unroll
    for (int mt = 0; mt < 3; mt++)
#pragma unroll
        for (int nt = 0; nt < 4; nt++)
#pragma unroll
            for (int r = 0; r < 4; r++) acc[mt][nt][r] = 0.0f;

#define ISSUE(S, K0) do { \
    uint32_t base = smb + (S) * 17920; \
    { int r = tid >> 2, c = tid & 3; \
      CP16(base + r * 80 + c * 16, Aw + (size_t)(m0 + r) * CDIM + (K0) + c * 8); } \
    if (tid < 128) { int idx = tid + 256; \
      int r = idx >> 2, c = idx & 3; \
      CP16(base + r * 80 + c * 16, Aw + (size_t)(m0 + r) * CDIM + (K0) + c * 8); } \
    _Pragma("unroll") for (int i = 0; i < 2; i++) { \
      int idx = tid + i * 256; \
      int r = idx >> 2, c = idx & 3; \
      CP16(base + 7680 + r * 80 + c * 16, Bx + (size_t)(n0 + r) * CDIM + (K0) + c * 8); } \
    CP_COMMIT(); \
} while (0)

    ISSUE(0, 0);
    ISSUE(1, 32);
    ISSUE(2, 64);

#pragma unroll 1
    for (int ch = 0; ch < 9; ch++) {
        if (ch <= 6) { CP_WAIT2(); } else if (ch == 7) { CP_WAIT1(); } else { CP_WAIT0(); }
        __syncthreads();
        if (ch < 6) ISSUE((ch + 3) & 3, (ch + 3) * 32);

        const uint32_t sb = smb + (ch & 3) * 17920;
#pragma unroll
        for (int s = 0; s < 2; s++) {
            const int so = s * 32;
            uint32_t af[3][4], bf[2][4];
#pragma unroll
            for (int mt = 0; mt < 3; mt++)
                ldsm4(af[mt][0], af[mt][1], af[mt][2], af[mt][3], sb + aoff[mt] + so);
#pragma unroll
            for (int p = 0; p < 2; p++)
                ldsm4(bf[p][0], bf[p][1], bf[p][2], bf[p][3], sb + boff[p] + so);
#pragma unroll
            for (int mt = 0; mt < 3; mt++)
#pragma unroll
                for (int nt = 0; nt < 4; nt++)
                    mma16(acc[mt][nt], af[mt][0], af[mt][1], af[mt][2], af[mt][3],
                          bf[nt >> 1][(nt & 1) * 2], bf[nt >> 1][(nt & 1) * 2 + 1]);
        }
    }
#undef ISSUE
    __syncthreads();

    float* stg = smf;                  // [96][133]
#pragma unroll
    for (int mt = 0; mt < 3; mt++) {
        int r0 = wm * 48 + mt * 16 + qr;
#pragma unroll
        for (int nt = 0; nt < 4; nt++) {
            int c0 = wn * 32 + nt * 8 + 2 * qc;
            stg[r0 * 133 + c0]           = acc[mt][nt][0];
            stg[r0 * 133 + c0 + 1]       = acc[mt][nt][1];
            stg[(r0 + 8) * 133 + c0]     = acc[mt][nt][2];
            stg[(r0 + 8) * 133 + c0 + 1] = acc[mt][nt][3];
        }
    }
    __syncthreads();

#pragma unroll
    for (int i = 0; i < 6; i++) {
        int idx = tid + i * 256;
        int t = idx / 12, q = idx - t * 12;
        uint32_t u0 = pack_h2(stg[(q * 8 + 0) * 133 + t], stg[(q * 8 + 1) * 133 + t]);
        uint32_t u1 = pack_h2(stg[(q * 8 + 2) * 133 + t], stg[(q * 8 + 3) * 133 + t]);
        uint32_t u2 = pack_h2(stg[(q * 8 + 4) * 133 + t], stg[(q * 8 + 5) * 133 + t]);
        uint32_t u3 = pack_h2(stg[(q * 8 + 6) * 133 + t], stg[(q * 8 + 7) * 133 + t]);
        *(uint4*)(Ch + (size_t)(n0 + t) * QKV_N + m0 + q * 8) = make_uint4(u0, u1, u2, u3);
    }
    if (m0 >= 2 * CDIM) {
#pragma unroll
        for (int i = 0; i < 6; i++) {
            int idx = tid + i * 256;
            int m = idx >> 4, c8 = (idx & 15) * 8;
            uint32_t u0 = pack_h2(stg[m * 133 + c8 + 0], stg[m * 133 + c8 + 1]);
            uint32_t u1 = pack_h2(stg[m * 133 + c8 + 2], stg[m * 133 + c8 + 3]);
            uint32_t u2 = pack_h2(stg[m * 133 + c8 + 4], stg[m * 133 + c8 + 5]);
            uint32_t u3 = pack_h2(stg[m * 133 + c8 + 6], stg[m * 133 + c8 + 7]);
            *(uint4*)(vc + ((size_t)bb * CDIM + (m0 - 2 * CDIM) + m) * L_TOT + l0 + c8)
                = make_uint4(u0, u1, u2, u3);
        }
    }
}

// ==================== GEMM2: out = y @ Wp^T + lcm^T @ Wp^T + bias ====================
#define G2_STAGE 26624
#define G2_SMEM  (2 * G2_STAGE)     // 53248

__global__ __launch_bounds__(256)
void gemm2_kernel(const __half* __restrict__ Aw, const __half* __restrict__ By,
                  const __half* __restrict__ lcm, float* __restrict__ Cf,
                  const float* __restrict__ bias) {
    extern __shared__ float smf[];
    const uint32_t smb = smem_u32_of(smf);
    const int tid = threadIdx.x, lane = tid & 31, warp = tid >> 5;
    const int qr = lane >> 2, qc = lane & 3;
    const int wm = warp & 1, wn = warp >> 1;
    const int n0 = blockIdx.x * 128;
    const int m0 = blockIdx.y * 96;
    const int bb = n0 >> 15;
    const int l0 = n0 & (L_TOT - 1);

    const int g8 = lane >> 3, lr = lane & 7;
    const int rowA = lr + (g8 & 1) * 8, colA = (g8 >> 1) * 16;
    const int rowB = lr + (g8 >> 1) * 8, colB = (g8 & 1) * 16;
    uint32_t aoff[3], byoff[2], lcoff[2];
#pragma unroll
    for (int mt = 0; mt < 3; mt++)
        aoff[mt] = (wm * 48 + mt * 16 + rowA) * 80 + colA;
#pragma unroll
    for (int p = 0; p < 2; p++) {
        byoff[p] = 7680 + (wn * 32 + p * 16 + rowB) * 80 + colB;
        lcoff[p] = 17920 + ((g8 & 1) * 8 + lr) * 272
                 + (wn * 32 + p * 16 + (g8 >> 1) * 8) * 2;
    }

    float acc[3][4][4];
#pragma unroll
    for (int mt = 0; mt < 3; mt++)
#pragma unroll
        for (int nt = 0; nt < 4; nt++)
#pragma unroll
            for (int r = 0; r < 4; r++) acc[mt][nt][r] = 0.0f;

#define ISSUE2(S, K0) do { \
    uint32_t base = smb + (S) * G2_STAGE; \
    { int r = tid >> 2, c = tid & 3; \
      CP16(base + r * 80 + c * 16, Aw + (size_t)(m0 + r) * CDIM + (K0) + c * 8); } \
    if (tid < 128) { int idx = tid + 256; \
      int r = idx >> 2, c = idx & 3; \
      CP16(base + r * 80 + c * 16, Aw + (size_t)(m0 + r) * CDIM + (K0) + c * 8); } \
    _Pragma("unroll") for (int i = 0; i < 2; i++) { \
      int idx = tid + i * 256; \
      int r = idx >> 2, c = idx & 3; \
      CP16(base + 7680 + r * 80 + c * 16, By + (size_t)(n0 + r) * CDIM + (K0) + c * 8); } \
    _Pragma("unroll") for (int i = 0; i < 2; i++) { \
      int idx = tid + i * 256; \
      int r = idx >> 4, c = idx & 15; \
      CP16(base + 17920 + r * 272 + c * 16, \
           lcm + ((size_t)bb * CDIM + (K0) + r) * L_TOT + l0 + c * 8); } \
    CP_COMMIT(); \
} while (0)

    ISSUE2(0, 0);
    ISSUE2(1, 32);

#pragma unroll 1
    for (int ch = 0; ch < 9; ch++) {
        if (ch < 8) { CP_WAIT1(); } else { CP_WAIT0(); }
        __syncthreads();

        const uint32_t sb = smb + (ch & 1) * G2_STAGE;
#pragma unroll
        for (int s = 0; s < 2; s++) {
            uint32_t af[3][4], bfY[2][4], bfL[2][4];
#pragma unroll
            for (int mt = 0; mt < 3; mt++)
                ldsm4(af[mt][0], af[mt][1], af[mt][2], af[mt][3], sb + aoff[mt] + s * 32);
#pragma unroll
            for (int p = 0; p < 2; p++)
                ldsm4(bfY[p][0], bfY[p][1], bfY[p][2], bfY[p][3], sb + byoff[p] + s * 32);
#pragma unroll
            for (int p = 0; p < 2; p++)
                ldsm4t(bfL[p][0], bfL[p][1], bfL[p][2], bfL[p][3], sb + lcoff[p] + s * 4352);
#pragma unroll
            for (int mt = 0; mt < 3; mt++)
#pragma unroll
                for (int nt = 0; nt < 4; nt++) {
                    mma16(acc[mt][nt], af[mt][0], af[mt][1], af[mt][2], af[mt][3],
                          bfY[nt >> 1][(nt & 1) * 2], bfY[nt >> 1][(nt & 1) * 2 + 1]);
                    mma16(acc[mt][nt], af[mt][0], af[mt][1], af[mt][2], af[mt][3],
                          bfL[nt >> 1][(nt & 1) * 2], bfL[nt >> 1][(nt & 1) * 2 + 1]);
                }
        }

        if (ch < 7) {
            __syncthreads();
            ISSUE2(ch & 1, (ch + 2) * 32);
        }
    }
#undef ISSUE2
    __syncthreads();

    float* stg = smf;                  // [96][133]
#pragma unroll
    for (int mt = 0; mt < 3; mt++) {
        int r0 = wm * 48 + mt * 16 + qr;
#pragma unroll
        for (int nt = 0; nt < 4; nt++) {
            int c0 = wn * 32 + nt * 8 + 2 * qc;
            stg[r0 * 133 + c0]           = acc[mt][nt][0];
            stg[r0 * 133 + c0 + 1]       = acc[mt][nt][1];
            stg[(r0 + 8) * 133 + c0]     = acc[mt][nt][2];
            stg[(r0 + 8) * 133 + c0 + 1] = acc[mt][nt][3];
        }
    }
    __syncthreads();

#pragma unroll
    for (int i = 0; i < 12; i++) {
        int idx = tid + i * 256;
        int t = idx / 24, q = idx - t * 24;
        float4 o;
        o.x = stg[(q * 4 + 0) * 133 + t] + bias[m0 + q * 4 + 0];
        o.y = stg[(q * 4 + 1) * 133 + t] + bias[m0 + q * 4 + 1];
        o.z = stg[(q * 4 + 2) * 133 + t] + bias[m0 + q * 4 + 2];
        o.w = stg[(q * 4 + 3) * 133 + t] + bias[m0 + q * 4 + 3];
        *(float4*)(Cf + (size_t)(n0 + t) * CDIM + m0 + q * 4) = o;
    }
}

// ==================== fused conv + attention ====================
// Conv plane layout: row stride 40 floats, data cols [4..35], halo at 3 / 36.
// Vectorized plane loads: thread (h = tid>>2, w8 = (tid&3)*8) loads uint4 (8 halves).
#define CONV_BLOCKS (BATCH * CDIM * 2)        // 1152
#define ATTN_BLOCKS 6144
#define FUSE_BLOCKS (CONV_BLOCKS + ATTN_BLOCKS)
#define CP_ROW 40
#define CP_PLANE (34 * CP_ROW)                // 1360 floats

__global__ __launch_bounds__(128)
void attn_conv_kernel(const __half* __restrict__ qkv, const float* __restrict__ biasb,
                      __half* __restrict__ y, const __half* __restrict__ vc,
                      const float* __restrict__ cw, const float* __restrict__ cb,
                      __half* __restrict__ lcm) {
    __shared__ float shm[7168];
    const int tid = threadIdx.x;

    if (blockIdx.x >= CONV_BLOCKS) {
        const int abid = blockIdx.x - CONV_BLOCKS;
        const int bi = abid / 2048;
        const int rem = abid - bi * 2048;
        const int b = rem >> 10;
        const int pair = rem & 1023;
        const int Dsp = c_Dsp[bi], Hsp = c_Hsp[bi], Wsp = c_Wsp[bi];
        const int nH = RESV / Hsp, nW = RESV / Wsp;
        const int g  = tid >> 6;
        const int tl = tid & 63;
        int widx = pair * 2 + g;
        int wblk = widx % nW; int tmp = widx / nW;
        int hblk = tmp % nH;  int dblk = tmp / nH;

        const int hb = tl >> 4;
        const int n  = tl & 15;
        const int HW = Hsp * Wsp;
        int dd = n / HW; int r = n - dd * HW;
        int hh = r / Wsp; int ww = r - hh * Wsp;
        int l = ((dblk * Dsp + dd) * RESV + hblk * Hsp + hh) * RESV + wblk * Wsp + ww;

        size_t rowbase = ((size_t)b * L_TOT + l) * QKV_N + bi * 96 + hb * HDIM;

        float* skr = shm + g * 1792;          // [64][28]
        float* svr = shm + 3584 + g * 1792;
        float q[HDIM];
        const float scale = 0.2041241452319315f;

        const uint4* qp = (const uint4*)(qkv + rowbase);
        const uint4* kp = (const uint4*)(qkv + rowbase + CDIM);
        const uint4* vp = (const uint4*)(qkv + rowbase + 2 * CDIM);
        const int srow = (hb * 16 + n) * 28;
#pragma unroll
        for (int j = 0; j < 3; j++) {
            uint4 uq = qp[j], uk = kp[j], uv = vp[j];
            __half2* hq = (__half2*)&uq;
            __half2* hk = (__half2*)&uk;
            __half2* hv = (__half2*)&uv;
            float kk[8], vv[8];
#pragma unroll
            for (int e = 0; e < 4; e++) {
                float2 fq = __half22float2(hq[e]);
                q[8 * j + 2 * e]     = fq.x * scale;
                q[8 * j + 2 * e + 1] = fq.y * scale;
                float2 fk = __half22float2(hk[e]);
                kk[2 * e] = fk.x; kk[2 * e + 1] = fk.y;
                float2 fv = __half22float2(hv[e]);
                vv[2 * e] = fv.x; vv[2 * e + 1] = fv.y;
            }
            *(float4*)(skr + srow + 8 * j)     = make_float4(kk[0], kk[1], kk[2], kk[3]);
            *(float4*)(skr + srow + 8 * j + 4) = make_float4(kk[4], kk[5], kk[6], kk[7]);
            *(float4*)(svr + srow + 8 * j)     = make_float4(vv[0], vv[1], vv[2], vv[3]);
            *(float4*)(svr + srow + 8 * j + 4) = make_float4(vv[4], vv[5], vv[6], vv[7]);
        }
        __syncthreads();

        const float* brow = biasb + (((size_t)bi * HB + hb) * NWIN + n) * NWIN;
        float lg[NWIN];
        float mx = -1e30f;
#pragma unroll
        for (int m = 0; m < NWIN; m++) {
            float s = brow[m];
            const float4* kr = (const float4*)(skr + (hb * 16 + m) * 28);
#pragma unroll
            for (int e4 = 0; e4 < 6; e4++) {
                float4 kk = kr[e4];
                s = fmaf(q[4 * e4 + 0], kk.x, s);
                s = fmaf(q[4 * e4 + 1], kk.y, s);
                s = fmaf(q[4 * e4 + 2], kk.z, s);
                s = fmaf(q[4 * e4 + 3], kk.w, s);
            }
            lg[m] = s;
            mx = fmaxf(mx, s);
        }
        float sum = 0.f;
#pragma unroll
        for (int m = 0; m < NWIN; m++) { lg[m] = __expf(lg[m] - mx); sum += lg[m]; }
        float inv = 1.0f / sum;

        float o[HDIM];
#pragma unroll
        for (int e = 0; e < HDIM; e++) o[e] = 0.f;
#pragma unroll
        for (int m = 0; m < NWIN; m++) {
            float w = lg[m] * inv;
            const float4* vr = (const float4*)(svr + (hb * 16 + m) * 28);
#pragma unroll
            for (int e4 = 0; e4 < 6; e4++) {
                float4 vv = vr[e4];
                o[4 * e4 + 0] = fmaf(w, vv.x, o[4 * e4 + 0]);
                o[4 * e4 + 1] = fmaf(w, vv.y, o[4 * e4 + 1]);
                o[4 * e4 + 2] = fmaf(w, vv.z, o[4 * e4 + 2]);
                o[4 * e4 + 3] = fmaf(w, vv.w, o[4 * e4 + 3]);
            }
        }

        __half* yp = y + ((size_t)b * L_TOT + l) * CDIM + bi * 96 + hb * HDIM;
#pragma unroll
        for (int j = 0; j < 3; j++) {
            uint32_t u0 = pack_h2(o[8 * j + 0], o[8 * j + 1]);
            uint32_t u1 = pack_h2(o[8 * j + 2], o[8 * j + 3]);
            uint32_t u2 = pack_h2(o[8 * j + 4], o[8 * j + 5]);
            uint32_t u3 = pack_h2(o[8 * j + 6], o[8 * j + 7]);
            *(uint4*)(yp + 8 * j) = make_uint4(u0, u1, u2, u3);
        }
        return;
    }

    // -------- depthwise 3x3x3 conv, d split in halves, vectorized loads --------
    const int bc  = blockIdx.x >> 1;
    const int dlo = (blockIdx.x & 1) * 16;
    const int dhi = dlo + 16;
    const int c = bc % CDIM;
    const __half* src = vc + (size_t)bc * L_TOT;
    __half* dst = lcm + (size_t)bc * L_TOT;

    float wt[27];
#pragma unroll
    for (int j = 0; j < 27; j++) wt[j] = cw[c * 27 + j];
    const float bias = cb[c];

    float* sp = shm;                             // 3 planes of [34][40]
    const int w = tid & 31;
    const int h0 = (tid >> 5) * 8;
    // vector-load mapping: 8 halves per thread
    const int vh = tid >> 2;                     // row 0..31
    const int vw = (tid & 3) * 8;                // col 0,8,16,24

    for (int i = tid; i < 3 * CP_PLANE; i += 128) sp[i] = 0.f;
    __syncthreads();

    // PLANE_LD: load plane `D` of src into slot (D%3) with uint4 (8 halves)
#define PLANE_LD(D) do { \
        float* sdst = sp + ((D) % 3) * CP_PLANE + (1 + vh) * CP_ROW + 4 + vw; \
        uint4 u = *(const uint4*)(src + (D) * 1024 + vh * 32 + vw); \
        __half2* hh = (__half2*)&u; \
        _Pragma("unroll") for (int e = 0; e < 4; e++) { \
            float2 f = __half22float2(hh[e]); \
            sdst[2 * e]     = f.x; \
            sdst[2 * e + 1] = f.y; } \
    } while (0)

    PLANE_LD(dlo);
    PLANE_LD(dlo + 1);
    if (dlo > 0) PLANE_LD(dlo - 1);
    __syncthreads();

#pragma unroll 1
    for (int d = dlo; d < dhi; d++) {
        const int bm = (d + 2) % 3;
        const int b0 = d % 3;
        const int bp = (d + 1) % 3;
        float acc[8];
#pragma unroll
        for (int jh = 0; jh < 8; jh++) acc[jh] = bias;

#define TAPS(BUF, KD) { \
        const float* P = sp + (BUF) * CP_PLANE + 3; \
        _Pragma("unroll") \
        for (int rr = 0; rr < 10; rr++) { \
            float va = P[(h0 + rr) * CP_ROW + w], vb = P[(h0 + rr) * CP_ROW + w + 1], \
                  vcx = P[(h0 + rr) * CP_ROW + w + 2]; \
            _Pragma("unroll") \
            for (int jh = 0; jh < 8; jh++) { \
                int kh = rr - jh; \
                if (kh >= 0 && kh < 3) { \
                    acc[jh] = fmaf(wt[(KD)*9 + kh*3 + 0], va, \
                              fmaf(wt[(KD)*9 + kh*3 + 1], vb, \
                              fmaf(wt[(KD)*9 + kh*3 + 2], vcx, acc[jh]))); \
                } \
            } \
        } }

        if (d > 0)  TAPS(bm, 0);
        TAPS(b0, 1);
        if (d < 31) TAPS(bp, 2);
#undef TAPS

#pragma unroll
        for (int jh = 0; jh < 8; jh++)
            dst[d * 1024 + (h0 + jh) * 32 + w] = __float2half(acc[jh]);

        __syncthreads();
        if (d + 2 < 32 && d < dhi - 1) {
            PLANE_LD(d + 2);
        }
        __syncthreads();
    }
#undef PLANE_LD
}

// ==================== launch ====================
extern "C" void kernel_launch(void* const* d_in, const int* in_sizes, int n_in,
                              void* d_out, int out_size) {
    const float* x      = (const float*)d_in[0];
    const float* w_qkv  = (const float*)d_in[4];
    const float* w_proj = (const float*)d_in[5];
    const float* b_proj = (const float*)d_in[6];
    const float* conv_w = (const float*)d_in[7];
    const float* conv_b = (const float*)d_in[8];
    const float* pos_w  = (const float*)d_in[9];
    const float* pos_b  = (const float*)d_in[10];
    const float* ln1g   = (const float*)d_in[11];
    const float* ln1b   = (const float*)d_in[12];
    const float* lin1w  = (const float*)d_in[13];
    const float* lin1b  = (const float*)d_in[14];
    const float* ln2g   = (const float*)d_in[15];
    const float* ln2b   = (const float*)d_in[16];
    const float* lin2w  = (const float*)d_in[17];
    const float* lin2b  = (const float*)d_in[18];
    const float* ln3g   = (const float*)d_in[19];
    const float* ln3b   = (const float*)d_in[20];
    const float* lin3w  = (const float*)d_in[21];
    const float* lin3b  = (const float*)d_in[22];
    const float* rpe    = (const float*)d_in[23];
    const int*   relidx = (const int*)d_in[24];
    float* out = (float*)d_out;

    __half *xhp, *qkvp, *yp, *vcp, *lcmp, *wqkvT, *wprojT;
    float *bp;
    cudaGetSymbolAddress((void**)&xhp,    g_xh);
    cudaGetSymbolAddress((void**)&qkvp,   g_qkv);
    cudaGetSymbolAddress((void**)&yp,     g_y);
    cudaGetSymbolAddress((void**)&bp,     g_bias);
    cudaGetSymbolAddress((void**)&vcp,    g_vc);
    cudaGetSymbolAddress((void**)&lcmp,   g_lcm);
    cudaGetSymbolAddress((void**)&wqkvT,  g_wqkvT);
    cudaGetSymbolAddress((void**)&wprojT, g_wprojT);

    cudaFuncSetAttribute(gemm1_kernel, cudaFuncAttributeMaxDynamicSharedMemorySize, G1_SMEM);
    cudaFuncSetAttribute(gemm2_kernel, cudaFuncAttributeMaxDynamicSharedMemorySize, G2_SMEM);

    // 0) fused prep: biasmlp + x->half + weight transposes
    prep_kernel<<<PREP_BLOCKS, 256>>>(x, xhp, w_qkv, wqkvT, w_proj, wprojT,
                                      rpe, pos_w, pos_b,
                                      ln1g, ln1b, lin1w, lin1b,
                                      ln2g, ln2b, lin2w, lin2b,
                                      ln3g, ln3b, lin3w, lin3b,
                                      relidx, bp);

    // 1) qkv = xh @ w_qkv  (also writes v channel-major into vc)
    gemm1_kernel<<<dim3(NROWS / 128, QKV_N / 96), 256, G1_SMEM>>>(wqkvT, xhp, qkvp, vcp);

    // 2) fused conv (front, vectorized loads) + attention (R12 layout)
    attn_conv_kernel<<<FUSE_BLOCKS, 128>>>(qkvp, bp, yp, vcp, conv_w, conv_b, lcmp);

    // 3) out = y @ Wp^T + lcm^T @ Wp^T + bias
    gemm2_kernel<<<dim3(NROWS / 128, CDIM / 96), 256, G2_SMEM>>>(wprojT, yp, lcmp, out, b_proj);
}